// round 4
// baseline (speedup 1.0000x reference)
#include <cuda_runtime.h>
#include <math_constants.h>

// Problem dims fixed by setup_inputs(): N=100000, E=1600000, Fin=128, H1=2, Fh=32, Fout=128
#define NN 100000
#define EE 1600000
#define ET (EE + NN)

// ---------------- scratch (static device memory; no allocations allowed) ----------------
__device__ int   g_is64;
__device__ int   g_deg[NN];
__device__ int   g_rowptr[NN + 1];
__device__ int   g_cursor[NN];
__device__ int   g_blksum[128];
__device__ int   g_csr[ET];
__device__ __align__(16) float g_h1[NN * 64];     // layer1 pre-activation features
__device__ float g_as1[NN * 2];                   // alpha_src layer1 [N,H1]
__device__ float g_ad1[NN * 2];                   // alpha_dst layer1
__device__ __align__(16) float g_h1p[NN * 64];    // relu(layer1 out)
__device__ __align__(16) float g_h2[NN * 128];    // layer2 pre-agg features
__device__ float g_as2[NN];
__device__ float g_ad2[NN];

__device__ __forceinline__ float lrelu(float x) { return x > 0.f ? x : 0.2f * x; }

__device__ __forceinline__ float wsum(float v) {
    #pragma unroll
    for (int o = 16; o; o >>= 1) v += __shfl_xor_sync(0xffffffffu, v, o);
    return v;
}
__device__ __forceinline__ float wmax(float v) {
    #pragma unroll
    for (int o = 16; o; o >>= 1) v = fmaxf(v, __shfl_xor_sync(0xffffffffu, v, o));
    return v;
}

// edge_index may arrive as int64 (reference dtype) or narrowed to int32 by the
// harness. Probe once per launch: if the data is int32, reading it as int64
// fuses two node indices -> value >= N with overwhelming probability.
__global__ void k_probe(const void* ei, int N) {
    if (threadIdx.x == 0 && blockIdx.x == 0) {
        const long long* p = (const long long*)ei;
        int ok = 1;
        #pragma unroll
        for (int i = 0; i < 16; i++) {
            long long v = p[i];
            if (v < 0 || v >= (long long)N) { ok = 0; break; }
        }
        g_is64 = ok;
    }
}

__device__ __forceinline__ void load_edge(const void* ei, int E, int e, int& s, int& d) {
    if (g_is64) {
        const long long* p = (const long long*)ei;
        s = (int)p[e]; d = (int)p[E + e];
    } else {
        const int* p = (const int*)ei;
        s = p[e]; d = p[E + e];
    }
}

// ---------------- CSR build ----------------
__global__ void k_init_deg(int N) {
    int i = blockIdx.x * blockDim.x + threadIdx.x;
    if (i < N) g_deg[i] = 1;  // self-loop
}

__global__ void k_count(const void* __restrict__ ei, int E, int N) {
    int e = blockIdx.x * blockDim.x + threadIdx.x;
    if (e >= E) return;
    int s, d;
    load_edge(ei, E, e, s, d);
    if ((unsigned)d < (unsigned)N) atomicAdd(&g_deg[d], 1);
}

__global__ void k_scan1(int N) {
    __shared__ int sm[1024];
    int idx = blockIdx.x * 1024 + threadIdx.x;
    int v = (idx < N) ? g_deg[idx] : 0;
    sm[threadIdx.x] = v;
    __syncthreads();
    #pragma unroll
    for (int off = 1; off < 1024; off <<= 1) {
        int t = (threadIdx.x >= off) ? sm[threadIdx.x - off] : 0;
        __syncthreads();
        sm[threadIdx.x] += t;
        __syncthreads();
    }
    if (idx < N) g_rowptr[idx] = sm[threadIdx.x] - v;  // exclusive
    if (threadIdx.x == 1023) g_blksum[blockIdx.x] = sm[1023];
}

__global__ void k_scan2(int nb) {
    int acc = 0;
    for (int i = 0; i < nb; i++) { int v = g_blksum[i]; g_blksum[i] = acc; acc += v; }
}

__global__ void k_scan3(int N, int total) {
    int idx = blockIdx.x * blockDim.x + threadIdx.x;
    if (idx > N) return;
    if (idx == N) { g_rowptr[N] = total; return; }
    int v = g_rowptr[idx] + g_blksum[idx >> 10];
    g_rowptr[idx] = v;
    g_cursor[idx] = v;
}

__global__ void k_fill(const void* __restrict__ ei, int E, int N) {
    int i = blockIdx.x * blockDim.x + threadIdx.x;
    if (i >= E + N) return;
    int s, d;
    if (i < E) {
        load_edge(ei, E, i, s, d);
        if ((unsigned)d >= (unsigned)N || (unsigned)s >= (unsigned)N) return;
    } else {
        s = d = i - E;
    }
    int pos = atomicAdd(&g_cursor[d], 1);
    g_csr[pos] = s;
}

// ---------------- GEMM1: h1 = x @ W1 [128x64], fused alpha_src/dst per head ----------------
// block: 256 threads = 64 cols x 4 row-slots; each thread computes rows s and s+4 (tile = 8 rows)
__global__ void k_gemm1(const float* __restrict__ x, const float* __restrict__ W1,
                        const float* __restrict__ as, const float* __restrict__ ad, int N) {
    __shared__ float Ws[128 * 64];   // 32 KB
    __shared__ float xs[8 * 128];    // 4 KB
    int t = threadIdx.x;
    int j = t & 63;
    int s = t >> 6;
    int lane = t & 31;
    for (int i = t; i < 128 * 64; i += 256) Ws[i] = W1[i];
    float asj = as[j], adj = ad[j];
    int head = j >> 5;
    int ntiles = (N + 7) >> 3;
    for (int tile = blockIdx.x; tile < ntiles; tile += gridDim.x) {
        int base = tile * 8;
        __syncthreads();
        for (int i = t; i < 1024; i += 256) {
            int r = i >> 7, c = i & 127;
            int row = base + r;
            xs[i] = (row < N) ? x[row * 128 + c] : 0.f;
        }
        __syncthreads();
        float accA = 0.f, accB = 0.f;
        const float* xA = &xs[s * 128];
        const float* xB = &xs[(s + 4) * 128];
        #pragma unroll 16
        for (int k = 0; k < 128; k++) {
            float w = Ws[k * 64 + j];
            accA += xA[k] * w;
            accB += xB[k] * w;
        }
        int rA = base + s, rB = base + s + 4;
        if (rA < N) g_h1[rA * 64 + j] = accA;
        if (rB < N) g_h1[rB * 64 + j] = accB;
        // warp = fixed (row-slot, head); lanes cover the 32 features of one head
        float pA = wsum(accA * asj), qA = wsum(accA * adj);
        float pB = wsum(accB * asj), qB = wsum(accB * adj);
        if (lane == 0) {
            if (rA < N) { g_as1[rA * 2 + head] = pA; g_ad1[rA * 2 + head] = qA; }
            if (rB < N) { g_as1[rB * 2 + head] = pB; g_ad1[rB * 2 + head] = qB; }
        }
    }
}

// ---------------- Layer1 aggregation: warp per dst node, H=2, F=32 each ----------------
__global__ void k_agg1(const float* __restrict__ b1, int N) {
    int node = blockIdx.x * 8 + (threadIdx.x >> 5);
    if (node >= N) return;
    int lane = threadIdx.x & 31;
    int start = g_rowptr[node], end = g_rowptr[node + 1];
    float ad0 = g_ad1[node * 2], ad1 = g_ad1[node * 2 + 1];
    // sweep 1: per-head max over incoming edges (lane-parallel)
    float m0 = -CUDART_INF_F, m1 = -CUDART_INF_F;
    for (int i = start + lane; i < end; i += 32) {
        int src = g_csr[i];
        m0 = fmaxf(m0, lrelu(g_as1[src * 2] + ad0));
        m1 = fmaxf(m1, lrelu(g_as1[src * 2 + 1] + ad1));
    }
    m0 = wmax(m0); m1 = wmax(m1);
    // sweep 2: accumulate exp sums and messages (whole warp per edge)
    float acc0 = 0.f, acc1 = 0.f, s0 = 0.f, s1 = 0.f;
    for (int i = start; i < end; i++) {
        int src = g_csr[i];
        float a0 = g_as1[src * 2], a1 = g_as1[src * 2 + 1];
        float ex0 = __expf(lrelu(a0 + ad0) - m0);
        float ex1 = __expf(lrelu(a1 + ad1) - m1);
        s0 += ex0; s1 += ex1;
        acc0 += ex0 * g_h1[src * 64 + lane];
        acc1 += ex1 * g_h1[src * 64 + 32 + lane];
    }
    float v0 = acc0 / s0 + b1[lane];
    float v1 = acc1 / s1 + b1[32 + lane];
    g_h1p[node * 64 + lane]      = fmaxf(v0, 0.f);
    g_h1p[node * 64 + 32 + lane] = fmaxf(v1, 0.f);
}

// ---------------- GEMM2: h2 = h1p @ W2 [64x128], fused alpha2 (H=1, F=128) ----------------
// block: 256 = 128 cols x 2 row-slots; each thread computes rows s and s+2 (tile = 4 rows)
__global__ void k_gemm2(const float* __restrict__ W2, const float* __restrict__ as,
                        const float* __restrict__ ad, int N) {
    __shared__ float Ws[64 * 128];  // 32 KB
    __shared__ float xs[4 * 64];
    __shared__ float red[4][4][2];
    int t = threadIdx.x;
    int j = t & 127;
    int s = t >> 7;
    int lane = t & 31;
    int warp = t >> 5;
    int jgrp = warp & 3;
    for (int i = t; i < 64 * 128; i += 256) Ws[i] = W2[i];
    float asj = as[j], adj = ad[j];
    int ntiles = (N + 3) >> 2;
    for (int tile = blockIdx.x; tile < ntiles; tile += gridDim.x) {
        int base = tile * 4;
        __syncthreads();
        if (t < 256) {
            int r = t >> 6, c = t & 63;
            int row = base + r;
            xs[t] = (row < N) ? g_h1p[row * 64 + c] : 0.f;
        }
        __syncthreads();
        float accA = 0.f, accB = 0.f;
        const float* xA = &xs[s * 64];
        const float* xB = &xs[(s + 2) * 64];
        #pragma unroll 16
        for (int k = 0; k < 64; k++) {
            float w = Ws[k * 128 + j];
            accA += xA[k] * w;
            accB += xB[k] * w;
        }
        int rA = base + s, rB = base + s + 2;
        if (rA < N) g_h2[rA * 128 + j] = accA;
        if (rB < N) g_h2[rB * 128 + j] = accB;
        float pA = wsum(accA * asj), qA = wsum(accA * adj);
        float pB = wsum(accB * asj), qB = wsum(accB * adj);
        if (lane == 0) {
            red[s][jgrp][0] = pA; red[s][jgrp][1] = qA;
            red[s + 2][jgrp][0] = pB; red[s + 2][jgrp][1] = qB;
        }
        __syncthreads();
        if (t < 8) {
            int slot = t >> 1, type = t & 1;
            float v = red[slot][0][type] + red[slot][1][type] + red[slot][2][type] + red[slot][3][type];
            int row = base + slot;
            if (row < N) {
                if (type == 0) g_as2[row] = v; else g_ad2[row] = v;
            }
        }
    }
}

// ---------------- Layer2 aggregation: warp per dst node, F=128 (float4 per lane) ----------------
__global__ void k_agg2(const float* __restrict__ b2, int N, float* __restrict__ out) {
    int node = blockIdx.x * 8 + (threadIdx.x >> 5);
    if (node >= N) return;
    int lane = threadIdx.x & 31;
    int start = g_rowptr[node], end = g_rowptr[node + 1];
    float ad = g_ad2[node];
    float m = -CUDART_INF_F;
    for (int i = start + lane; i < end; i += 32) {
        int src = g_csr[i];
        m = fmaxf(m, lrelu(g_as2[src] + ad));
    }
    m = wmax(m);
    const float4* h4 = (const float4*)g_h2;
    float4 acc = make_float4(0.f, 0.f, 0.f, 0.f);
    float ssum = 0.f;
    for (int i = start; i < end; i++) {
        int src = g_csr[i];
        float ex = __expf(lrelu(g_as2[src] + ad) - m);
        ssum += ex;
        float4 v = h4[src * 32 + lane];
        acc.x += ex * v.x; acc.y += ex * v.y; acc.z += ex * v.z; acc.w += ex * v.w;
    }
    float inv = 1.f / ssum;
    const float4* b4 = (const float4*)b2;
    float4 bb = b4[lane];
    float4 o;
    o.x = acc.x * inv + bb.x;
    o.y = acc.y * inv + bb.y;
    o.z = acc.z * inv + bb.z;
    o.w = acc.w * inv + bb.w;
    ((float4*)out)[node * 32 + lane] = o;
}

// ---------------- launch ----------------
extern "C" void kernel_launch(void* const* d_in, const int* in_sizes, int n_in,
                              void* d_out, int out_size) {
    const float* x   = (const float*)d_in[0];
    const void*  ei  = d_in[1];
    const float* W1  = (const float*)d_in[2];
    const float* as1 = (const float*)d_in[3];
    const float* ad1 = (const float*)d_in[4];
    const float* b1  = (const float*)d_in[5];
    const float* W2  = (const float*)d_in[6];
    const float* as2 = (const float*)d_in[7];
    const float* ad2 = (const float*)d_in[8];
    const float* b2  = (const float*)d_in[9];
    float* out = (float*)d_out;

    int N = in_sizes[0] / 128;
    int E = in_sizes[1] / 2;

    k_probe<<<1, 32>>>(ei, N);
    k_init_deg<<<(N + 255) / 256, 256>>>(N);
    k_count<<<(E + 255) / 256, 256>>>(ei, E, N);
    int nb = (N + 1023) / 1024;
    k_scan1<<<nb, 1024>>>(N);
    k_scan2<<<1, 1>>>(nb);
    k_scan3<<<(N + 1 + 255) / 256, 256>>>(N, E + N);
    k_fill<<<(E + N + 255) / 256, 256>>>(ei, E, N);
    k_gemm1<<<1480, 256>>>(x, W1, as1, ad1, N);
    k_agg1<<<(N + 7) / 8, 256>>>(b1, N);
    k_gemm2<<<1480, 256>>>(W2, as2, ad2, N);
    k_agg2<<<(N + 7) / 8, 256>>>(b2, N, out);
}

// round 5
// speedup vs baseline: 1.0014x; 1.0014x over previous
#include <cuda_runtime.h>
#include <math_constants.h>

// Problem dims fixed by setup_inputs(): N=100000, E=1600000, Fin=128, H1=2, Fh=32, Fout=128
#define NN 100000
#define EE 1600000
#define ET (EE + NN)

// ---------------- scratch (static device memory; no allocations allowed) ----------------
__device__ int   g_is64;
__device__ int   g_deg[NN];
__device__ int   g_rowptr[NN + 1];
__device__ int   g_cursor[NN];
__device__ int   g_blksum[128];
__device__ int   g_csr[ET];
__device__ __align__(16) float g_h1[NN * 64];     // layer1 pre-activation features
__device__ float g_as1[NN * 2];                   // alpha_src layer1 [N,H1]
__device__ float g_ad1[NN * 2];                   // alpha_dst layer1
__device__ __align__(16) float g_h1p[NN * 64];    // relu(layer1 out)
__device__ __align__(16) float g_h2[NN * 128];    // layer2 pre-agg features
__device__ float g_as2[NN];
__device__ float g_ad2[NN];

__device__ __forceinline__ float lrelu(float x) { return x > 0.f ? x : 0.2f * x; }

__device__ __forceinline__ float wsum(float v) {
    #pragma unroll
    for (int o = 16; o; o >>= 1) v += __shfl_xor_sync(0xffffffffu, v, o);
    return v;
}
__device__ __forceinline__ float wmax(float v) {
    #pragma unroll
    for (int o = 16; o; o >>= 1) v = fmaxf(v, __shfl_xor_sync(0xffffffffu, v, o));
    return v;
}

// edge_index may arrive as int64 (reference dtype) or narrowed to int32 by the
// harness. Probe once per launch: if the data is int32, reading it as int64
// fuses two node indices -> value >= N with overwhelming probability.
__global__ void k_probe(const void* ei, int N) {
    if (threadIdx.x == 0 && blockIdx.x == 0) {
        const long long* p = (const long long*)ei;
        int ok = 1;
        #pragma unroll
        for (int i = 0; i < 16; i++) {
            long long v = p[i];
            if (v < 0 || v >= (long long)N) { ok = 0; break; }
        }
        g_is64 = ok;
    }
}

__device__ __forceinline__ void load_edge(const void* ei, int E, int e, int& s, int& d) {
    if (g_is64) {
        const long long* p = (const long long*)ei;
        s = (int)p[e]; d = (int)p[E + e];
    } else {
        const int* p = (const int*)ei;
        s = p[e]; d = p[E + e];
    }
}

// ---------------- CSR build ----------------
__global__ void k_init_deg(int N) {
    int i = blockIdx.x * blockDim.x + threadIdx.x;
    if (i < N) g_deg[i] = 1;  // self-loop
}

__global__ void k_count(const void* __restrict__ ei, int E, int N) {
    int e = blockIdx.x * blockDim.x + threadIdx.x;
    if (e >= E) return;
    int s, d;
    load_edge(ei, E, e, s, d);
    if ((unsigned)d < (unsigned)N) atomicAdd(&g_deg[d], 1);
}

__global__ void k_scan1(int N) {
    __shared__ int sm[1024];
    int idx = blockIdx.x * 1024 + threadIdx.x;
    int v = (idx < N) ? g_deg[idx] : 0;
    sm[threadIdx.x] = v;
    __syncthreads();
    #pragma unroll
    for (int off = 1; off < 1024; off <<= 1) {
        int t = (threadIdx.x >= off) ? sm[threadIdx.x - off] : 0;
        __syncthreads();
        sm[threadIdx.x] += t;
        __syncthreads();
    }
    if (idx < N) g_rowptr[idx] = sm[threadIdx.x] - v;  // exclusive
    if (threadIdx.x == 1023) g_blksum[blockIdx.x] = sm[1023];
}

__global__ void k_scan2(int nb) {
    int acc = 0;
    for (int i = 0; i < nb; i++) { int v = g_blksum[i]; g_blksum[i] = acc; acc += v; }
}

__global__ void k_scan3(int N, int total) {
    int idx = blockIdx.x * blockDim.x + threadIdx.x;
    if (idx > N) return;
    if (idx == N) { g_rowptr[N] = total; return; }
    int v = g_rowptr[idx] + g_blksum[idx >> 10];
    g_rowptr[idx] = v;
    g_cursor[idx] = v;
}

__global__ void k_fill(const void* __restrict__ ei, int E, int N) {
    int i = blockIdx.x * blockDim.x + threadIdx.x;
    if (i >= E + N) return;
    int s, d;
    if (i < E) {
        load_edge(ei, E, i, s, d);
        if ((unsigned)d >= (unsigned)N || (unsigned)s >= (unsigned)N) return;
    } else {
        s = d = i - E;
    }
    int pos = atomicAdd(&g_cursor[d], 1);
    g_csr[pos] = s;
}

// ---------------- GEMM1: h1 = x @ W1 [128x64], fused alpha_src/dst per head ----------------
// block: 256 threads = 64 cols x 4 row-slots; each thread computes rows s and s+4 (tile = 8 rows)
__global__ void k_gemm1(const float* __restrict__ x, const float* __restrict__ W1,
                        const float* __restrict__ as, const float* __restrict__ ad, int N) {
    __shared__ float Ws[128 * 64];   // 32 KB
    __shared__ float xs[8 * 128];    // 4 KB
    int t = threadIdx.x;
    int j = t & 63;
    int s = t >> 6;
    int lane = t & 31;
    for (int i = t; i < 128 * 64; i += 256) Ws[i] = W1[i];
    float asj = as[j], adj = ad[j];
    int head = j >> 5;
    int ntiles = (N + 7) >> 3;
    for (int tile = blockIdx.x; tile < ntiles; tile += gridDim.x) {
        int base = tile * 8;
        __syncthreads();
        for (int i = t; i < 1024; i += 256) {
            int r = i >> 7, c = i & 127;
            int row = base + r;
            xs[i] = (row < N) ? x[row * 128 + c] : 0.f;
        }
        __syncthreads();
        float accA = 0.f, accB = 0.f;
        const float* xA = &xs[s * 128];
        const float* xB = &xs[(s + 4) * 128];
        #pragma unroll 16
        for (int k = 0; k < 128; k++) {
            float w = Ws[k * 64 + j];
            accA += xA[k] * w;
            accB += xB[k] * w;
        }
        int rA = base + s, rB = base + s + 4;
        if (rA < N) g_h1[rA * 64 + j] = accA;
        if (rB < N) g_h1[rB * 64 + j] = accB;
        // warp = fixed (row-slot, head); lanes cover the 32 features of one head
        float pA = wsum(accA * asj), qA = wsum(accA * adj);
        float pB = wsum(accB * asj), qB = wsum(accB * adj);
        if (lane == 0) {
            if (rA < N) { g_as1[rA * 2 + head] = pA; g_ad1[rA * 2 + head] = qA; }
            if (rB < N) { g_as1[rB * 2 + head] = pB; g_ad1[rB * 2 + head] = qB; }
        }
    }
}

// ---------------- Layer1 aggregation: warp per dst node, H=2, F=32 each ----------------
__global__ void k_agg1(const float* __restrict__ b1, int N) {
    int node = blockIdx.x * 8 + (threadIdx.x >> 5);
    if (node >= N) return;
    int lane = threadIdx.x & 31;
    int start = g_rowptr[node], end = g_rowptr[node + 1];
    float ad0 = g_ad1[node * 2], ad1 = g_ad1[node * 2 + 1];
    // sweep 1: per-head max over incoming edges (lane-parallel)
    float m0 = -CUDART_INF_F, m1 = -CUDART_INF_F;
    for (int i = start + lane; i < end; i += 32) {
        int src = g_csr[i];
        m0 = fmaxf(m0, lrelu(g_as1[src * 2] + ad0));
        m1 = fmaxf(m1, lrelu(g_as1[src * 2 + 1] + ad1));
    }
    m0 = wmax(m0); m1 = wmax(m1);
    // sweep 2: accumulate exp sums and messages (whole warp per edge)
    float acc0 = 0.f, acc1 = 0.f, s0 = 0.f, s1 = 0.f;
    for (int i = start; i < end; i++) {
        int src = g_csr[i];
        float a0 = g_as1[src * 2], a1 = g_as1[src * 2 + 1];
        float ex0 = __expf(lrelu(a0 + ad0) - m0);
        float ex1 = __expf(lrelu(a1 + ad1) - m1);
        s0 += ex0; s1 += ex1;
        acc0 += ex0 * g_h1[src * 64 + lane];
        acc1 += ex1 * g_h1[src * 64 + 32 + lane];
    }
    float v0 = acc0 / s0 + b1[lane];
    float v1 = acc1 / s1 + b1[32 + lane];
    g_h1p[node * 64 + lane]      = fmaxf(v0, 0.f);
    g_h1p[node * 64 + 32 + lane] = fmaxf(v1, 0.f);
}

// ---------------- GEMM2: h2 = h1p @ W2 [64x128], fused alpha2 (H=1, F=128) ----------------
// block: 256 = 128 cols x 2 row-slots; each thread computes rows s and s+2 (tile = 4 rows)
__global__ void k_gemm2(const float* __restrict__ W2, const float* __restrict__ as,
                        const float* __restrict__ ad, int N) {
    __shared__ float Ws[64 * 128];  // 32 KB
    __shared__ float xs[4 * 64];
    __shared__ float red[4][4][2];
    int t = threadIdx.x;
    int j = t & 127;
    int s = t >> 7;
    int lane = t & 31;
    int warp = t >> 5;
    int jgrp = warp & 3;
    for (int i = t; i < 64 * 128; i += 256) Ws[i] = W2[i];
    float asj = as[j], adj = ad[j];
    int ntiles = (N + 3) >> 2;
    for (int tile = blockIdx.x; tile < ntiles; tile += gridDim.x) {
        int base = tile * 4;
        __syncthreads();
        if (t < 256) {
            int r = t >> 6, c = t & 63;
            int row = base + r;
            xs[t] = (row < N) ? g_h1p[row * 64 + c] : 0.f;
        }
        __syncthreads();
        float accA = 0.f, accB = 0.f;
        const float* xA = &xs[s * 64];
        const float* xB = &xs[(s + 2) * 64];
        #pragma unroll 16
        for (int k = 0; k < 64; k++) {
            float w = Ws[k * 128 + j];
            accA += xA[k] * w;
            accB += xB[k] * w;
        }
        int rA = base + s, rB = base + s + 2;
        if (rA < N) g_h2[rA * 128 + j] = accA;
        if (rB < N) g_h2[rB * 128 + j] = accB;
        float pA = wsum(accA * asj), qA = wsum(accA * adj);
        float pB = wsum(accB * asj), qB = wsum(accB * adj);
        if (lane == 0) {
            red[s][jgrp][0] = pA; red[s][jgrp][1] = qA;
            red[s + 2][jgrp][0] = pB; red[s + 2][jgrp][1] = qB;
        }
        __syncthreads();
        if (t < 8) {
            int slot = t >> 1, type = t & 1;
            float v = red[slot][0][type] + red[slot][1][type] + red[slot][2][type] + red[slot][3][type];
            int row = base + slot;
            if (row < N) {
                if (type == 0) g_as2[row] = v; else g_ad2[row] = v;
            }
        }
    }
}

// ---------------- Layer2 aggregation: warp per dst node, F=128 (float4 per lane) ----------------
__global__ void k_agg2(const float* __restrict__ b2, int N, float* __restrict__ out) {
    int node = blockIdx.x * 8 + (threadIdx.x >> 5);
    if (node >= N) return;
    int lane = threadIdx.x & 31;
    int start = g_rowptr[node], end = g_rowptr[node + 1];
    float ad = g_ad2[node];
    float m = -CUDART_INF_F;
    for (int i = start + lane; i < end; i += 32) {
        int src = g_csr[i];
        m = fmaxf(m, lrelu(g_as2[src] + ad));
    }
    m = wmax(m);
    const float4* h4 = (const float4*)g_h2;
    float4 acc = make_float4(0.f, 0.f, 0.f, 0.f);
    float ssum = 0.f;
    for (int i = start; i < end; i++) {
        int src = g_csr[i];
        float ex = __expf(lrelu(g_as2[src] + ad) - m);
        ssum += ex;
        float4 v = h4[src * 32 + lane];
        acc.x += ex * v.x; acc.y += ex * v.y; acc.z += ex * v.z; acc.w += ex * v.w;
    }
    float inv = 1.f / ssum;
    const float4* b4 = (const float4*)b2;
    float4 bb = b4[lane];
    float4 o;
    o.x = acc.x * inv + bb.x;
    o.y = acc.y * inv + bb.y;
    o.z = acc.z * inv + bb.z;
    o.w = acc.w * inv + bb.w;
    ((float4*)out)[node * 32 + lane] = o;
}

// ---------------- launch ----------------
extern "C" void kernel_launch(void* const* d_in, const int* in_sizes, int n_in,
                              void* d_out, int out_size) {
    const float* x   = (const float*)d_in[0];
    const void*  ei  = d_in[1];
    const float* W1  = (const float*)d_in[2];
    const float* as1 = (const float*)d_in[3];
    const float* ad1 = (const float*)d_in[4];
    const float* b1  = (const float*)d_in[5];
    const float* W2  = (const float*)d_in[6];
    const float* as2 = (const float*)d_in[7];
    const float* ad2 = (const float*)d_in[8];
    const float* b2  = (const float*)d_in[9];
    float* out = (float*)d_out;

    int N = in_sizes[0] / 128;
    int E = in_sizes[1] / 2;

    k_probe<<<1, 32>>>(ei, N);
    k_init_deg<<<(N + 255) / 256, 256>>>(N);
    k_count<<<(E + 255) / 256, 256>>>(ei, E, N);
    int nb = (N + 1023) / 1024;
    k_scan1<<<nb, 1024>>>(N);
    k_scan2<<<1, 1>>>(nb);
    k_scan3<<<(N + 1 + 255) / 256, 256>>>(N, E + N);
    k_fill<<<(E + N + 255) / 256, 256>>>(ei, E, N);
    k_gemm1<<<1480, 256>>>(x, W1, as1, ad1, N);
    k_agg1<<<(N + 7) / 8, 256>>>(b1, N);
    k_gemm2<<<1480, 256>>>(W2, as2, ad2, N);
    k_agg2<<<(N + 7) / 8, 256>>>(b2, N, out);
}

// round 6
// speedup vs baseline: 1.1311x; 1.1295x over previous
#include <cuda_runtime.h>
#include <math_constants.h>

// Problem dims fixed by setup_inputs(): N=100000, E=1600000, Fin=128, H1=2, Fh=32, Fout=128
#define NN 100000
#define EE 1600000
#define ET (EE + NN)

// ---------------- scratch (static device memory; no allocations allowed) ----------------
__device__ int   g_is64;
__device__ int   g_deg[NN];
__device__ int   g_rowptr[NN + 1];
__device__ int   g_cursor[NN];
__device__ int   g_blksum[128];
__device__ int   g_csr[ET];
__device__ __align__(16) float g_h1[NN * 64];     // layer1 pre-activation features
__device__ float g_as1[NN * 2];                   // alpha_src layer1 [N,H1]
__device__ float g_ad1[NN * 2];                   // alpha_dst layer1
__device__ __align__(16) float g_h1p[NN * 64];    // relu(layer1 out)
__device__ __align__(16) float g_h2[NN * 128];    // layer2 pre-agg features
__device__ float g_as2[NN];
__device__ float g_ad2[NN];

__device__ __forceinline__ float lrelu(float x) { return x > 0.f ? x : 0.2f * x; }

__device__ __forceinline__ float wmax(float v) {
    #pragma unroll
    for (int o = 16; o; o >>= 1) v = fmaxf(v, __shfl_xor_sync(0xffffffffu, v, o));
    return v;
}

// edge_index may arrive as int64 (reference dtype) or narrowed to int32 by the
// harness. Probe once per launch: if the data is int32, reading it as int64
// fuses two node indices -> value >= N with overwhelming probability.
__global__ void k_probe(const void* ei, int N) {
    if (threadIdx.x == 0 && blockIdx.x == 0) {
        const long long* p = (const long long*)ei;
        int ok = 1;
        #pragma unroll
        for (int i = 0; i < 16; i++) {
            long long v = p[i];
            if (v < 0 || v >= (long long)N) { ok = 0; break; }
        }
        g_is64 = ok;
    }
}

__device__ __forceinline__ void load_edge(const void* ei, int E, int e, int& s, int& d) {
    if (g_is64) {
        const long long* p = (const long long*)ei;
        s = (int)p[e]; d = (int)p[E + e];
    } else {
        const int* p = (const int*)ei;
        s = p[e]; d = p[E + e];
    }
}

// ---------------- CSR build ----------------
__global__ void k_init_deg(int N) {
    int i = blockIdx.x * blockDim.x + threadIdx.x;
    if (i < N) g_deg[i] = 1;  // self-loop
}

__global__ void k_count(const void* __restrict__ ei, int E, int N) {
    int e = blockIdx.x * blockDim.x + threadIdx.x;
    if (e >= E) return;
    int s, d;
    load_edge(ei, E, e, s, d);
    if ((unsigned)d < (unsigned)N) atomicAdd(&g_deg[d], 1);
}

__global__ void k_scan1(int N) {
    __shared__ int sm[1024];
    int idx = blockIdx.x * 1024 + threadIdx.x;
    int v = (idx < N) ? g_deg[idx] : 0;
    sm[threadIdx.x] = v;
    __syncthreads();
    #pragma unroll
    for (int off = 1; off < 1024; off <<= 1) {
        int t = (threadIdx.x >= off) ? sm[threadIdx.x - off] : 0;
        __syncthreads();
        sm[threadIdx.x] += t;
        __syncthreads();
    }
    if (idx < N) g_rowptr[idx] = sm[threadIdx.x] - v;  // exclusive
    if (threadIdx.x == 1023) g_blksum[blockIdx.x] = sm[1023];
}

__global__ void k_scan2(int nb) {
    int acc = 0;
    for (int i = 0; i < nb; i++) { int v = g_blksum[i]; g_blksum[i] = acc; acc += v; }
}

__global__ void k_scan3(int N, int total) {
    int idx = blockIdx.x * blockDim.x + threadIdx.x;
    if (idx > N) return;
    if (idx == N) { g_rowptr[N] = total; return; }
    int v = g_rowptr[idx] + g_blksum[idx >> 10];
    g_rowptr[idx] = v;
    g_cursor[idx] = v;
}

__global__ void k_fill(const void* __restrict__ ei, int E, int N) {
    int i = blockIdx.x * blockDim.x + threadIdx.x;
    if (i >= E + N) return;
    int s, d;
    if (i < E) {
        load_edge(ei, E, i, s, d);
        if ((unsigned)d >= (unsigned)N || (unsigned)s >= (unsigned)N) return;
    } else {
        s = d = i - E;
    }
    int pos = atomicAdd(&g_cursor[d], 1);
    g_csr[pos] = s;
}

// ---------------- GEMM1: h1 = x @ W1 [128x64], fused alpha epilogue ----------------
// Tile 64 rows x 64 cols. 256 threads; each thread computes a 4x4 register block.
// x tile transposed into smem (xs[k][row], stride 68); W streamed via L1 (32 KB, read-only).
// Inner loop per k: 1 LDG.128 (W) + 1 LDS.128 (x) + 16 FFMA -> FFMA-pipe bound.
__global__ void __launch_bounds__(256) k_gemm1(const float* __restrict__ x,
                                               const float* __restrict__ W1,
                                               const float* __restrict__ as,
                                               const float* __restrict__ ad, int N) {
    __shared__ float xs[128 * 68];   // 34.8 KB
    int t = threadIdx.x;
    int tx = t & 15;                 // col group: cols tx*4 .. tx*4+3
    int ty = t >> 4;                 // row group: rows ty*4 .. ty*4+3
    int head = tx >> 3;
    int base = blockIdx.x * 64;

    float4 as4 = ((const float4*)as)[tx];
    float4 ad4 = ((const float4*)ad)[tx];

    // load + transpose x tile: xs[k*68 + row]
    for (int i = t; i < 64 * 128; i += 256) {
        int row = i >> 7, k = i & 127;
        int r = base + row;
        xs[k * 68 + row] = (r < N) ? x[r * 128 + k] : 0.f;
    }
    __syncthreads();

    float acc[4][4] = {};
    #pragma unroll 4
    for (int k = 0; k < 128; k++) {
        float4 w = __ldg((const float4*)&W1[k * 64 + tx * 4]);
        float4 xv = *(const float4*)&xs[k * 68 + ty * 4];
        acc[0][0] += xv.x * w.x; acc[0][1] += xv.x * w.y; acc[0][2] += xv.x * w.z; acc[0][3] += xv.x * w.w;
        acc[1][0] += xv.y * w.x; acc[1][1] += xv.y * w.y; acc[1][2] += xv.y * w.z; acc[1][3] += xv.y * w.w;
        acc[2][0] += xv.z * w.x; acc[2][1] += xv.z * w.y; acc[2][2] += xv.z * w.z; acc[2][3] += xv.z * w.w;
        acc[3][0] += xv.w * w.x; acc[3][1] += xv.w * w.y; acc[3][2] += xv.w * w.z; acc[3][3] += xv.w * w.w;
    }

    #pragma unroll
    for (int r = 0; r < 4; r++) {
        int row = base + ty * 4 + r;
        float4 h = make_float4(acc[r][0], acc[r][1], acc[r][2], acc[r][3]);
        if (row < N) *(float4*)&g_h1[row * 64 + tx * 4] = h;
        float p = h.x * as4.x + h.y * as4.y + h.z * as4.z + h.w * as4.w;
        float q = h.x * ad4.x + h.y * ad4.y + h.z * ad4.z + h.w * ad4.w;
        // reduce across the 8 tx-lanes of this head (lane bits 0..2 = tx bits 0..2)
        #pragma unroll
        for (int o = 1; o <= 4; o <<= 1) {
            p += __shfl_xor_sync(0xffffffffu, p, o);
            q += __shfl_xor_sync(0xffffffffu, q, o);
        }
        if ((tx & 7) == 0 && row < N) {
            g_as1[row * 2 + head] = p;
            g_ad1[row * 2 + head] = q;
        }
    }
}

// ---------------- Layer1 aggregation: warp per dst node, H=2, F=32 each ----------------
__global__ void k_agg1(const float* __restrict__ b1, int N) {
    int node = blockIdx.x * 8 + (threadIdx.x >> 5);
    if (node >= N) return;
    int lane = threadIdx.x & 31;
    int start = g_rowptr[node], end = g_rowptr[node + 1];
    float ad0 = g_ad1[node * 2], ad1 = g_ad1[node * 2 + 1];
    // sweep 1: per-head max over incoming edges (lane-parallel)
    float m0 = -CUDART_INF_F, m1 = -CUDART_INF_F;
    for (int i = start + lane; i < end; i += 32) {
        int src = g_csr[i];
        m0 = fmaxf(m0, lrelu(g_as1[src * 2] + ad0));
        m1 = fmaxf(m1, lrelu(g_as1[src * 2 + 1] + ad1));
    }
    m0 = wmax(m0); m1 = wmax(m1);
    // sweep 2: accumulate exp sums and messages (whole warp per edge)
    float acc0 = 0.f, acc1 = 0.f, s0 = 0.f, s1 = 0.f;
    #pragma unroll 4
    for (int i = start; i < end; i++) {
        int src = g_csr[i];
        float a0 = g_as1[src * 2], a1 = g_as1[src * 2 + 1];
        float ex0 = __expf(lrelu(a0 + ad0) - m0);
        float ex1 = __expf(lrelu(a1 + ad1) - m1);
        s0 += ex0; s1 += ex1;
        acc0 += ex0 * g_h1[src * 64 + lane];
        acc1 += ex1 * g_h1[src * 64 + 32 + lane];
    }
    float v0 = acc0 / s0 + b1[lane];
    float v1 = acc1 / s1 + b1[32 + lane];
    g_h1p[node * 64 + lane]      = fmaxf(v0, 0.f);
    g_h1p[node * 64 + 32 + lane] = fmaxf(v1, 0.f);
}

// ---------------- GEMM2: h2 = h1p @ W2 [64x128], fused alpha2 (H=1, F=128) ----------------
// Tile 64 rows x 128 cols. 256 threads; each thread computes a 4x8 register block.
__global__ void __launch_bounds__(256) k_gemm2(const float* __restrict__ W2,
                                               const float* __restrict__ as,
                                               const float* __restrict__ ad, int N) {
    __shared__ float xs[64 * 68];    // 17.4 KB
    int t = threadIdx.x;
    int tx = t & 15;                 // col group: cols tx*8 .. tx*8+7
    int ty = t >> 4;                 // row group: rows ty*4 .. ty*4+3
    int base = blockIdx.x * 64;

    float4 asA = ((const float4*)as)[tx * 2],     asB = ((const float4*)as)[tx * 2 + 1];
    float4 adA = ((const float4*)ad)[tx * 2],     adB = ((const float4*)ad)[tx * 2 + 1];

    for (int i = t; i < 64 * 64; i += 256) {
        int row = i >> 6, k = i & 63;
        int r = base + row;
        xs[k * 68 + row] = (r < N) ? g_h1p[r * 64 + k] : 0.f;
    }
    __syncthreads();

    float accA[4][4] = {}, accB[4][4] = {};
    #pragma unroll 4
    for (int k = 0; k < 64; k++) {
        float4 wa = __ldg((const float4*)&W2[k * 128 + tx * 8]);
        float4 wb = __ldg((const float4*)&W2[k * 128 + tx * 8 + 4]);
        float4 xv = *(const float4*)&xs[k * 68 + ty * 4];
        float xr[4] = {xv.x, xv.y, xv.z, xv.w};
        #pragma unroll
        for (int r = 0; r < 4; r++) {
            accA[r][0] += xr[r] * wa.x; accA[r][1] += xr[r] * wa.y;
            accA[r][2] += xr[r] * wa.z; accA[r][3] += xr[r] * wa.w;
            accB[r][0] += xr[r] * wb.x; accB[r][1] += xr[r] * wb.y;
            accB[r][2] += xr[r] * wb.z; accB[r][3] += xr[r] * wb.w;
        }
    }

    #pragma unroll
    for (int r = 0; r < 4; r++) {
        int row = base + ty * 4 + r;
        float4 hA = make_float4(accA[r][0], accA[r][1], accA[r][2], accA[r][3]);
        float4 hB = make_float4(accB[r][0], accB[r][1], accB[r][2], accB[r][3]);
        if (row < N) {
            *(float4*)&g_h2[row * 128 + tx * 8]     = hA;
            *(float4*)&g_h2[row * 128 + tx * 8 + 4] = hB;
        }
        float p = hA.x * asA.x + hA.y * asA.y + hA.z * asA.z + hA.w * asA.w
                + hB.x * asB.x + hB.y * asB.y + hB.z * asB.z + hB.w * asB.w;
        float q = hA.x * adA.x + hA.y * adA.y + hA.z * adA.z + hA.w * adA.w
                + hB.x * adB.x + hB.y * adB.y + hB.z * adB.z + hB.w * adB.w;
        // reduce across all 16 tx-lanes (lane bits 0..3)
        #pragma unroll
        for (int o = 1; o <= 8; o <<= 1) {
            p += __shfl_xor_sync(0xffffffffu, p, o);
            q += __shfl_xor_sync(0xffffffffu, q, o);
        }
        if (tx == 0 && row < N) { g_as2[row] = p; g_ad2[row] = q; }
    }
}

// ---------------- Layer2 aggregation: warp per dst node, F=128 (float4 per lane) ----------------
__global__ void k_agg2(const float* __restrict__ b2, int N, float* __restrict__ out) {
    int node = blockIdx.x * 8 + (threadIdx.x >> 5);
    if (node >= N) return;
    int lane = threadIdx.x & 31;
    int start = g_rowptr[node], end = g_rowptr[node + 1];
    float ad = g_ad2[node];
    float m = -CUDART_INF_F;
    for (int i = start + lane; i < end; i += 32) {
        int src = g_csr[i];
        m = fmaxf(m, lrelu(g_as2[src] + ad));
    }
    m = wmax(m);
    const float4* h4 = (const float4*)g_h2;
    float4 acc = make_float4(0.f, 0.f, 0.f, 0.f);
    float ssum = 0.f;
    #pragma unroll 4
    for (int i = start; i < end; i++) {
        int src = g_csr[i];
        float ex = __expf(lrelu(g_as2[src] + ad) - m);
        ssum += ex;
        float4 v = h4[src * 32 + lane];
        acc.x += ex * v.x; acc.y += ex * v.y; acc.z += ex * v.z; acc.w += ex * v.w;
    }
    float inv = 1.f / ssum;
    const float4* b4 = (const float4*)b2;
    float4 bb = b4[lane];
    float4 o;
    o.x = acc.x * inv + bb.x;
    o.y = acc.y * inv + bb.y;
    o.z = acc.z * inv + bb.z;
    o.w = acc.w * inv + bb.w;
    ((float4*)out)[node * 32 + lane] = o;
}

// ---------------- launch ----------------
extern "C" void kernel_launch(void* const* d_in, const int* in_sizes, int n_in,
                              void* d_out, int out_size) {
    const float* x   = (const float*)d_in[0];
    const void*  ei  = d_in[1];
    const float* W1  = (const float*)d_in[2];
    const float* as1 = (const float*)d_in[3];
    const float* ad1 = (const float*)d_in[4];
    const float* b1  = (const float*)d_in[5];
    const float* W2  = (const float*)d_in[6];
    const float* as2 = (const float*)d_in[7];
    const float* ad2 = (const float*)d_in[8];
    const float* b2  = (const float*)d_in[9];
    float* out = (float*)d_out;

    int N = in_sizes[0] / 128;
    int E = in_sizes[1] / 2;

    k_probe<<<1, 32>>>(ei, N);
    k_init_deg<<<(N + 255) / 256, 256>>>(N);
    k_count<<<(E + 255) / 256, 256>>>(ei, E, N);
    int nb = (N + 1023) / 1024;
    k_scan1<<<nb, 1024>>>(N);
    k_scan2<<<1, 1>>>(nb);
    k_scan3<<<(N + 1 + 255) / 256, 256>>>(N, E + N);
    k_fill<<<(E + N + 255) / 256, 256>>>(ei, E, N);
    int ng = (N + 63) / 64;
    k_gemm1<<<ng, 256>>>(x, W1, as1, ad1, N);
    k_agg1<<<(N + 7) / 8, 256>>>(b1, N);
    k_gemm2<<<ng, 256>>>(W2, as2, ad2, N);
    k_agg2<<<(N + 7) / 8, 256>>>(b2, N, out);
}

// round 8
// speedup vs baseline: 1.2272x; 1.0849x over previous
#include <cuda_runtime.h>
#include <cuda_fp16.h>
#include <math_constants.h>

// Problem dims fixed by setup_inputs(): N=100000, E=1600000, Fin=128, H1=2, Fh=32, Fout=128
#define NN 100000
#define EE 1600000
#define ET (EE + NN)

// ---------------- scratch (static device memory; no allocations allowed) ----------------
__device__ int   g_is64;
__device__ int   g_deg[NN];
__device__ int   g_rowptr[NN + 1];
__device__ int   g_cursor[NN];
__device__ int   g_blksum[128];
__device__ int   g_csr[ET];
__device__ __align__(16) float  g_h1[NN * 64];    // layer1 pre-agg features (fp32)
__device__ float g_as1[NN * 2];                   // alpha_src layer1 [N,H1]
__device__ float g_ad1[NN * 2];                   // alpha_dst layer1
__device__ __align__(16) float  g_h1p[NN * 64];   // relu(layer1 out)
__device__ __align__(16) __half g_h2h[NN * 128];  // layer2 pre-agg features (fp16 gather table)
__device__ float g_as2[NN];
__device__ float g_ad2[NN];

__device__ __forceinline__ float lrelu(float x) { return x > 0.f ? x : 0.2f * x; }

__device__ __forceinline__ unsigned h2_to_u(__half2 h) {
    union { __half2 h; unsigned u; } c; c.h = h; return c.u;
}
__device__ __forceinline__ __half2 u_to_h2(unsigned u) {
    union { __half2 h; unsigned u; } c; c.u = u; return c.h;
}

// edge_index may arrive as int64 (reference dtype) or narrowed to int32 by the
// harness. Probe once: int32 data read as int64 fuses two node indices ->
// value >= N with overwhelming probability.
__device__ __forceinline__ void load_edge(const void* ei, int E, int e, int& s, int& d) {
    if (g_is64) {
        const long long* p = (const long long*)ei;
        s = (int)p[e]; d = (int)p[E + e];
    } else {
        const int* p = (const int*)ei;
        s = p[e]; d = p[E + e];
    }
}

// ---------------- CSR build ----------------
__global__ void k_init_deg(const void* ei, int N) {
    int i = blockIdx.x * blockDim.x + threadIdx.x;
    if (i < N) g_deg[i] = 1;  // self-loop
    if (i == 0) {             // dtype probe (visible to later kernels at launch boundary)
        const long long* p = (const long long*)ei;
        int ok = 1;
        #pragma unroll
        for (int k = 0; k < 16; k++) {
            long long v = p[k];
            if (v < 0 || v >= (long long)N) { ok = 0; break; }
        }
        g_is64 = ok;
    }
}

__global__ void k_count(const void* __restrict__ ei, int E, int N) {
    int e = blockIdx.x * blockDim.x + threadIdx.x;
    if (e >= E) return;
    int d;
    if (g_is64) d = (int)((const long long*)ei)[E + e];
    else        d = ((const int*)ei)[E + e];
    if ((unsigned)d < (unsigned)N) atomicAdd(&g_deg[d], 1);
}

__global__ void k_scan1(int N) {
    __shared__ int sm[1024];
    int idx = blockIdx.x * 1024 + threadIdx.x;
    int v = (idx < N) ? g_deg[idx] : 0;
    sm[threadIdx.x] = v;
    __syncthreads();
    #pragma unroll
    for (int off = 1; off < 1024; off <<= 1) {
        int t = (threadIdx.x >= off) ? sm[threadIdx.x - off] : 0;
        __syncthreads();
        sm[threadIdx.x] += t;
        __syncthreads();
    }
    if (idx < N) g_rowptr[idx] = sm[threadIdx.x] - v;  // exclusive
    if (threadIdx.x == 1023) g_blksum[blockIdx.x] = sm[1023];
}

// one-block parallel exclusive scan of block sums (nb <= 128)
__global__ void k_scan2(int nb) {
    int t = threadIdx.x;           // 128 threads
    int lane = t & 31, w = t >> 5;
    int orig = (t < nb) ? g_blksum[t] : 0;
    int v = orig;
    #pragma unroll
    for (int o = 1; o < 32; o <<= 1) {
        int u = __shfl_up_sync(0xffffffffu, v, o);
        if (lane >= o) v += u;
    }
    __shared__ int ws[4];
    if (lane == 31) ws[w] = v;
    __syncthreads();
    int add = 0;
    #pragma unroll
    for (int i = 0; i < 4; i++) if (i < w) add += ws[i];
    v += add;
    if (t < nb) g_blksum[t] = v - orig;  // exclusive
}

__global__ void k_scan3(int N, int total) {
    int idx = blockIdx.x * blockDim.x + threadIdx.x;
    if (idx > N) return;
    if (idx == N) { g_rowptr[N] = total; return; }
    int v = g_rowptr[idx] + g_blksum[idx >> 10];
    g_rowptr[idx] = v;
    g_cursor[idx] = v;
}

__global__ void k_fill(const void* __restrict__ ei, int E, int N) {
    int i = blockIdx.x * blockDim.x + threadIdx.x;
    if (i >= E + N) return;
    int s, d;
    if (i < E) {
        load_edge(ei, E, i, s, d);
        if ((unsigned)d >= (unsigned)N || (unsigned)s >= (unsigned)N) return;
    } else {
        s = d = i - E;
    }
    int pos = atomicAdd(&g_cursor[d], 1);
    g_csr[pos] = s;
}

// ---------------- GEMM1: h1 = x @ W1 [128x64], fused alpha epilogue ----------------
// Tile 64 rows x 64 cols. 256 threads; 4x4 register block per thread.
__global__ void __launch_bounds__(256) k_gemm1(const float* __restrict__ x,
                                               const float* __restrict__ W1,
                                               const float* __restrict__ as,
                                               const float* __restrict__ ad, int N) {
    __shared__ float xs[128 * 68];   // 34.8 KB, transposed x tile
    int t = threadIdx.x;
    int tx = t & 15;                 // cols tx*4 .. tx*4+3
    int ty = t >> 4;                 // rows ty*4 .. ty*4+3
    int head = tx >> 3;
    int base = blockIdx.x * 64;

    float4 as4 = ((const float4*)as)[tx];
    float4 ad4 = ((const float4*)ad)[tx];

    for (int i = t; i < 64 * 128; i += 256) {
        int row = i >> 7, k = i & 127;
        int r = base + row;
        xs[k * 68 + row] = (r < N) ? x[r * 128 + k] : 0.f;
    }
    __syncthreads();

    float acc[4][4] = {};
    #pragma unroll 4
    for (int k = 0; k < 128; k++) {
        float4 w = __ldg((const float4*)&W1[k * 64 + tx * 4]);
        float4 xv = *(const float4*)&xs[k * 68 + ty * 4];
        acc[0][0] += xv.x * w.x; acc[0][1] += xv.x * w.y; acc[0][2] += xv.x * w.z; acc[0][3] += xv.x * w.w;
        acc[1][0] += xv.y * w.x; acc[1][1] += xv.y * w.y; acc[1][2] += xv.y * w.z; acc[1][3] += xv.y * w.w;
        acc[2][0] += xv.z * w.x; acc[2][1] += xv.z * w.y; acc[2][2] += xv.z * w.z; acc[2][3] += xv.z * w.w;
        acc[3][0] += xv.w * w.x; acc[3][1] += xv.w * w.y; acc[3][2] += xv.w * w.z; acc[3][3] += xv.w * w.w;
    }

    #pragma unroll
    for (int r = 0; r < 4; r++) {
        int row = base + ty * 4 + r;
        float4 h = make_float4(acc[r][0], acc[r][1], acc[r][2], acc[r][3]);
        if (row < N) *(float4*)&g_h1[row * 64 + tx * 4] = h;
        float p = h.x * as4.x + h.y * as4.y + h.z * as4.z + h.w * as4.w;
        float q = h.x * ad4.x + h.y * ad4.y + h.z * ad4.z + h.w * ad4.w;
        #pragma unroll
        for (int o = 1; o <= 4; o <<= 1) {
            p += __shfl_xor_sync(0xffffffffu, p, o);
            q += __shfl_xor_sync(0xffffffffu, q, o);
        }
        if ((tx & 7) == 0 && row < N) {
            g_as1[row * 2 + head] = p;
            g_ad1[row * 2 + head] = q;
        }
    }
}

// ---------------- Layer1 aggregation: warp per dst node, single sweep (no-max softmax) ----------------
// alpha logits are O(few sigma) -> exp never overflows; ratio identical to max-sub form.
__global__ void k_agg1(const float* __restrict__ b1, int N) {
    int node = blockIdx.x * 8 + (threadIdx.x >> 5);
    if (node >= N) return;
    int lane = threadIdx.x & 31;
    int start = g_rowptr[node], end = g_rowptr[node + 1];
    float ad0 = g_ad1[node * 2], ad1 = g_ad1[node * 2 + 1];
    float acc0 = 0.f, acc1 = 0.f, s0 = 0.f, s1 = 0.f;
    #pragma unroll 4
    for (int i = start; i < end; i++) {
        int src = g_csr[i];
        float ex0 = __expf(lrelu(g_as1[src * 2] + ad0));
        float ex1 = __expf(lrelu(g_as1[src * 2 + 1] + ad1));
        s0 += ex0; s1 += ex1;
        acc0 += ex0 * g_h1[src * 64 + lane];
        acc1 += ex1 * g_h1[src * 64 + 32 + lane];
    }
    float v0 = acc0 / s0 + b1[lane];
    float v1 = acc1 / s1 + b1[32 + lane];
    g_h1p[node * 64 + lane]      = fmaxf(v0, 0.f);
    g_h1p[node * 64 + 32 + lane] = fmaxf(v1, 0.f);
}

// ---------------- GEMM2: h2 = h1p @ W2 [64x128] -> fp16 table, fused alpha2 ----------------
// Tile 64 rows x 128 cols. 256 threads; 4x8 register block per thread.
__global__ void __launch_bounds__(256) k_gemm2(const float* __restrict__ W2,
                                               const float* __restrict__ as,
                                               const float* __restrict__ ad, int N) {
    __shared__ float xs[64 * 68];    // 17.4 KB
    int t = threadIdx.x;
    int tx = t & 15;                 // cols tx*8 .. tx*8+7
    int ty = t >> 4;                 // rows ty*4 .. ty*4+3
    int base = blockIdx.x * 64;

    float4 asA = ((const float4*)as)[tx * 2], asB = ((const float4*)as)[tx * 2 + 1];
    float4 adA = ((const float4*)ad)[tx * 2], adB = ((const float4*)ad)[tx * 2 + 1];

    for (int i = t; i < 64 * 64; i += 256) {
        int row = i >> 6, k = i & 63;
        int r = base + row;
        xs[k * 68 + row] = (r < N) ? g_h1p[r * 64 + k] : 0.f;
    }
    __syncthreads();

    float accA[4][4] = {}, accB[4][4] = {};
    #pragma unroll 4
    for (int k = 0; k < 64; k++) {
        float4 wa = __ldg((const float4*)&W2[k * 128 + tx * 8]);
        float4 wb = __ldg((const float4*)&W2[k * 128 + tx * 8 + 4]);
        float4 xv = *(const float4*)&xs[k * 68 + ty * 4];
        float xr[4] = {xv.x, xv.y, xv.z, xv.w};
        #pragma unroll
        for (int r = 0; r < 4; r++) {
            accA[r][0] += xr[r] * wa.x; accA[r][1] += xr[r] * wa.y;
            accA[r][2] += xr[r] * wa.z; accA[r][3] += xr[r] * wa.w;
            accB[r][0] += xr[r] * wb.x; accB[r][1] += xr[r] * wb.y;
            accB[r][2] += xr[r] * wb.z; accB[r][3] += xr[r] * wb.w;
        }
    }

    #pragma unroll
    for (int r = 0; r < 4; r++) {
        int row = base + ty * 4 + r;
        float4 hA = make_float4(accA[r][0], accA[r][1], accA[r][2], accA[r][3]);
        float4 hB = make_float4(accB[r][0], accB[r][1], accB[r][2], accB[r][3]);
        if (row < N) {
            // pack 8 fp32 -> 8 fp16 -> one 16B store
            uint4 pk;
            pk.x = h2_to_u(__floats2half2_rn(hA.x, hA.y));
            pk.y = h2_to_u(__floats2half2_rn(hA.z, hA.w));
            pk.z = h2_to_u(__floats2half2_rn(hB.x, hB.y));
            pk.w = h2_to_u(__floats2half2_rn(hB.z, hB.w));
            *(uint4*)&g_h2h[row * 128 + tx * 8] = pk;
        }
        float p = hA.x * asA.x + hA.y * asA.y + hA.z * asA.z + hA.w * asA.w
                + hB.x * asB.x + hB.y * asB.y + hB.z * asB.z + hB.w * asB.w;
        float q = hA.x * adA.x + hA.y * adA.y + hA.z * adA.z + hA.w * adA.w
                + hB.x * adB.x + hB.y * adB.y + hB.z * adB.z + hB.w * adB.w;
        #pragma unroll
        for (int o = 1; o <= 8; o <<= 1) {
            p += __shfl_xor_sync(0xffffffffu, p, o);
            q += __shfl_xor_sync(0xffffffffu, q, o);
        }
        if (tx == 0 && row < N) { g_as2[row] = p; g_ad2[row] = q; }
    }
}

// ---------------- Layer2 aggregation: warp per dst node, fp16 gather, single sweep ----------------
__global__ void k_agg2(const float* __restrict__ b2, int N, float* __restrict__ out) {
    int node = blockIdx.x * 8 + (threadIdx.x >> 5);
    if (node >= N) return;
    int lane = threadIdx.x & 31;
    int start = g_rowptr[node], end = g_rowptr[node + 1];
    float ad = g_ad2[node];
    float4 acc = make_float4(0.f, 0.f, 0.f, 0.f);
    float ssum = 0.f;
    #pragma unroll 4
    for (int i = start; i < end; i++) {
        int src = g_csr[i];
        float ex = __expf(lrelu(g_as2[src] + ad));
        ssum += ex;
        uint2 pk = *(const uint2*)&g_h2h[src * 128 + lane * 4];  // 4 halves
        float2 v0 = __half22float2(u_to_h2(pk.x));
        float2 v1 = __half22float2(u_to_h2(pk.y));
        acc.x += ex * v0.x; acc.y += ex * v0.y;
        acc.z += ex * v1.x; acc.w += ex * v1.y;
    }
    float inv = 1.f / ssum;
    float4 bb = ((const float4*)b2)[lane];
    float4 o;
    o.x = acc.x * inv + bb.x;
    o.y = acc.y * inv + bb.y;
    o.z = acc.z * inv + bb.z;
    o.w = acc.w * inv + bb.w;
    ((float4*)out)[node * 32 + lane] = o;
}

// ---------------- launch ----------------
extern "C" void kernel_launch(void* const* d_in, const int* in_sizes, int n_in,
                              void* d_out, int out_size) {
    const float* x   = (const float*)d_in[0];
    const void*  ei  = d_in[1];
    const float* W1  = (const float*)d_in[2];
    const float* as1 = (const float*)d_in[3];
    const float* ad1 = (const float*)d_in[4];
    const float* b1  = (const float*)d_in[5];
    const float* W2  = (const float*)d_in[6];
    const float* as2 = (const float*)d_in[7];
    const float* ad2 = (const float*)d_in[8];
    const float* b2  = (const float*)d_in[9];
    float* out = (float*)d_out;

    int N = in_sizes[0] / 128;
    int E = in_sizes[1] / 2;

    k_init_deg<<<(N + 255) / 256, 256>>>(ei, N);
    k_count<<<(E + 255) / 256, 256>>>(ei, E, N);
    int nb = (N + 1023) / 1024;
    k_scan1<<<nb, 1024>>>(N);
    k_scan2<<<1, 128>>>(nb);
    k_scan3<<<(N + 1 + 255) / 256, 256>>>(N, E + N);
    k_fill<<<(E + N + 255) / 256, 256>>>(ei, E, N);
    int ng = (N + 63) / 64;
    k_gemm1<<<ng, 256>>>(x, W1, as1, ad1, N);
    k_agg1<<<(N + 7) / 8, 256>>>(b1, N);
    k_gemm2<<<ng, 256>>>(W2, as2, ad2, N);
    k_agg2<<<(N + 7) / 8, 256>>>(b2, N, out);
}

// round 9
// speedup vs baseline: 1.2949x; 1.0552x over previous
#include <cuda_runtime.h>
#include <cuda_fp16.h>
#include <math_constants.h>

// Problem dims fixed by setup_inputs(): N=100000, E=1600000, Fin=128, H1=2, Fh=32, Fout=128
#define NN 100000
#define EE 1600000
#define ET (EE + NN)

// ---------------- scratch (static device memory; no allocations allowed) ----------------
__device__ int   g_is64;
__device__ int   g_deg[NN];
__device__ int   g_rowptr[NN + 1];
__device__ int   g_cursor[NN];
__device__ int   g_blksum[128];
__device__ int   g_csr[ET];
__device__ __align__(16) __half g_h1h[NN * 64];   // layer1 pre-agg features (fp16 gather table)
__device__ float g_as1[NN * 2];                   // alpha_src layer1 [N,H1]
__device__ float g_ad1[NN * 2];                   // alpha_dst layer1
__device__ __align__(16) float  g_h1p[NN * 64];   // relu(layer1 out), fp32 (linear reads in gemm2)
__device__ __align__(16) __half g_h2h[NN * 128];  // layer2 pre-agg features (fp16 gather table)
__device__ float g_as2[NN];
__device__ float g_ad2[NN];

__device__ __forceinline__ float lrelu(float x) { return x > 0.f ? x : 0.2f * x; }

__device__ __forceinline__ unsigned h2_to_u(__half2 h) {
    union { __half2 h; unsigned u; } c; c.h = h; return c.u;
}
__device__ __forceinline__ __half2 u_to_h2(unsigned u) {
    union { __half2 h; unsigned u; } c; c.u = u; return c.h;
}

// edge_index may arrive as int64 (reference dtype) or narrowed to int32 by the
// harness. Probe once: int32 data read as int64 fuses two node indices ->
// value >= N with overwhelming probability.
__device__ __forceinline__ void load_edge(const void* ei, int E, int e, int& s, int& d) {
    if (g_is64) {
        const long long* p = (const long long*)ei;
        s = (int)p[e]; d = (int)p[E + e];
    } else {
        const int* p = (const int*)ei;
        s = p[e]; d = p[E + e];
    }
}

// ---------------- CSR build ----------------
__global__ void k_init_deg(const void* ei, int N) {
    int i = blockIdx.x * blockDim.x + threadIdx.x;
    if (i < N) g_deg[i] = 1;  // self-loop
    if (i == 0) {             // dtype probe (visible to later kernels at launch boundary)
        const long long* p = (const long long*)ei;
        int ok = 1;
        #pragma unroll
        for (int k = 0; k < 16; k++) {
            long long v = p[k];
            if (v < 0 || v >= (long long)N) { ok = 0; break; }
        }
        g_is64 = ok;
    }
}

__global__ void k_count(const void* __restrict__ ei, int E, int N) {
    int e = blockIdx.x * blockDim.x + threadIdx.x;
    if (e >= E) return;
    int d;
    if (g_is64) d = (int)((const long long*)ei)[E + e];
    else        d = ((const int*)ei)[E + e];
    if ((unsigned)d < (unsigned)N) atomicAdd(&g_deg[d], 1);
}

__global__ void k_scan1(int N) {
    __shared__ int sm[1024];
    int idx = blockIdx.x * 1024 + threadIdx.x;
    int v = (idx < N) ? g_deg[idx] : 0;
    sm[threadIdx.x] = v;
    __syncthreads();
    #pragma unroll
    for (int off = 1; off < 1024; off <<= 1) {
        int t = (threadIdx.x >= off) ? sm[threadIdx.x - off] : 0;
        __syncthreads();
        sm[threadIdx.x] += t;
        __syncthreads();
    }
    if (idx < N) g_rowptr[idx] = sm[threadIdx.x] - v;  // exclusive
    if (threadIdx.x == 1023) g_blksum[blockIdx.x] = sm[1023];
}

// scan3 with inline block-sum prefix: each block reduces blksum[0..b-1] itself (<=98 values)
__global__ void k_scan3(int N, int total) {
    __shared__ int ws[4];
    __shared__ int sh_prefix;
    int b = blockIdx.x;
    int t = threadIdx.x;
    if (t < 128) {
        int lane = t & 31, w = t >> 5;
        int v = (t < b) ? g_blksum[t] : 0;   // b <= 97 < 128
        #pragma unroll
        for (int o = 16; o; o >>= 1) v += __shfl_xor_sync(0xffffffffu, v, o);
        if (lane == 0) ws[w] = v;
    }
    __syncthreads();
    if (t == 0) sh_prefix = ws[0] + ws[1] + ws[2] + ws[3];
    __syncthreads();
    int idx = b * 1024 + t;
    if (idx > N) return;
    if (idx == N) { g_rowptr[N] = total; return; }
    int v = g_rowptr[idx] + sh_prefix;
    g_rowptr[idx] = v;
    g_cursor[idx] = v;
}

__global__ void k_fill(const void* __restrict__ ei, int E, int N) {
    int i = blockIdx.x * blockDim.x + threadIdx.x;
    if (i >= E + N) return;
    int s, d;
    if (i < E) {
        load_edge(ei, E, i, s, d);
        if ((unsigned)d >= (unsigned)N || (unsigned)s >= (unsigned)N) return;
    } else {
        s = d = i - E;
    }
    int pos = atomicAdd(&g_cursor[d], 1);
    g_csr[pos] = s;
}

// ---------------- GEMM1: h1 = x @ W1 [128x64] -> fp16 table, fused alpha epilogue ----------------
// Tile 64 rows x 64 cols. 256 threads; 4x4 register block per thread.
__global__ void __launch_bounds__(256) k_gemm1(const float* __restrict__ x,
                                               const float* __restrict__ W1,
                                               const float* __restrict__ as,
                                               const float* __restrict__ ad, int N) {
    __shared__ float xs[128 * 68];   // 34.8 KB, transposed x tile
    int t = threadIdx.x;
    int tx = t & 15;                 // cols tx*4 .. tx*4+3
    int ty = t >> 4;                 // rows ty*4 .. ty*4+3
    int head = tx >> 3;
    int base = blockIdx.x * 64;

    float4 as4 = ((const float4*)as)[tx];
    float4 ad4 = ((const float4*)ad)[tx];

    for (int i = t; i < 64 * 128; i += 256) {
        int row = i >> 7, k = i & 127;
        int r = base + row;
        xs[k * 68 + row] = (r < N) ? x[r * 128 + k] : 0.f;
    }
    __syncthreads();

    float acc[4][4] = {};
    #pragma unroll 4
    for (int k = 0; k < 128; k++) {
        float4 w = __ldg((const float4*)&W1[k * 64 + tx * 4]);
        float4 xv = *(const float4*)&xs[k * 68 + ty * 4];
        acc[0][0] += xv.x * w.x; acc[0][1] += xv.x * w.y; acc[0][2] += xv.x * w.z; acc[0][3] += xv.x * w.w;
        acc[1][0] += xv.y * w.x; acc[1][1] += xv.y * w.y; acc[1][2] += xv.y * w.z; acc[1][3] += xv.y * w.w;
        acc[2][0] += xv.z * w.x; acc[2][1] += xv.z * w.y; acc[2][2] += xv.z * w.z; acc[2][3] += xv.z * w.w;
        acc[3][0] += xv.w * w.x; acc[3][1] += xv.w * w.y; acc[3][2] += xv.w * w.z; acc[3][3] += xv.w * w.w;
    }

    #pragma unroll
    for (int r = 0; r < 4; r++) {
        int row = base + ty * 4 + r;
        float4 h = make_float4(acc[r][0], acc[r][1], acc[r][2], acc[r][3]);
        if (row < N) {
            uint2 pk;
            pk.x = h2_to_u(__floats2half2_rn(h.x, h.y));
            pk.y = h2_to_u(__floats2half2_rn(h.z, h.w));
            *(uint2*)&g_h1h[row * 64 + tx * 4] = pk;
        }
        float p = h.x * as4.x + h.y * as4.y + h.z * as4.z + h.w * as4.w;
        float q = h.x * ad4.x + h.y * ad4.y + h.z * ad4.z + h.w * ad4.w;
        #pragma unroll
        for (int o = 1; o <= 4; o <<= 1) {
            p += __shfl_xor_sync(0xffffffffu, p, o);
            q += __shfl_xor_sync(0xffffffffu, q, o);
        }
        if ((tx & 7) == 0 && row < N) {
            g_as1[row * 2 + head] = p;
            g_ad1[row * 2 + head] = q;
        }
    }
}

// ---------------- Layer1 aggregation: warp per dst node, fp16 gather, single sweep ----------------
// Lane l owns features {2l, 2l+1} (one half2). Lanes 0-15 -> head0, 16-31 -> head1:
// each lane computes only its own head's exp and normalizer.
__global__ void k_agg1(const float* __restrict__ b1, int N) {
    int node = blockIdx.x * 8 + (threadIdx.x >> 5);
    if (node >= N) return;
    int lane = threadIdx.x & 31;
    int hsel = lane >> 4;
    int start = g_rowptr[node], end = g_rowptr[node + 1];
    float adh = g_ad1[node * 2 + hsel];
    float2 acc = make_float2(0.f, 0.f);
    float ssum = 0.f;
    #pragma unroll 4
    for (int i = start; i < end; i++) {
        int src = g_csr[i];
        float a = g_as1[src * 2 + hsel];
        float ex = __expf(lrelu(a + adh));
        ssum += ex;
        float2 v = __half22float2(*(const __half2*)&g_h1h[src * 64 + lane * 2]);
        acc.x += ex * v.x; acc.y += ex * v.y;
    }
    float inv = 1.f / ssum;
    float2 bb = ((const float2*)b1)[lane];
    float2 o = make_float2(fmaxf(acc.x * inv + bb.x, 0.f), fmaxf(acc.y * inv + bb.y, 0.f));
    *(float2*)&g_h1p[node * 64 + lane * 2] = o;
}

// ---------------- GEMM2: h2 = h1p @ W2 [64x128] -> fp16 table, fused alpha2 ----------------
// Tile 64 rows x 128 cols. 256 threads; 4x8 register block per thread.
__global__ void __launch_bounds__(256) k_gemm2(const float* __restrict__ W2,
                                               const float* __restrict__ as,
                                               const float* __restrict__ ad, int N) {
    __shared__ float xs[64 * 68];    // 17.4 KB
    int t = threadIdx.x;
    int tx = t & 15;                 // cols tx*8 .. tx*8+7
    int ty = t >> 4;                 // rows ty*4 .. ty*4+3
    int base = blockIdx.x * 64;

    float4 asA = ((const float4*)as)[tx * 2], asB = ((const float4*)as)[tx * 2 + 1];
    float4 adA = ((const float4*)ad)[tx * 2], adB = ((const float4*)ad)[tx * 2 + 1];

    for (int i = t; i < 64 * 64; i += 256) {
        int row = i >> 6, k = i & 63;
        int r = base + row;
        xs[k * 68 + row] = (r < N) ? g_h1p[r * 64 + k] : 0.f;
    }
    __syncthreads();

    float accA[4][4] = {}, accB[4][4] = {};
    #pragma unroll 4
    for (int k = 0; k < 64; k++) {
        float4 wa = __ldg((const float4*)&W2[k * 128 + tx * 8]);
        float4 wb = __ldg((const float4*)&W2[k * 128 + tx * 8 + 4]);
        float4 xv = *(const float4*)&xs[k * 68 + ty * 4];
        float xr[4] = {xv.x, xv.y, xv.z, xv.w};
        #pragma unroll
        for (int r = 0; r < 4; r++) {
            accA[r][0] += xr[r] * wa.x; accA[r][1] += xr[r] * wa.y;
            accA[r][2] += xr[r] * wa.z; accA[r][3] += xr[r] * wa.w;
            accB[r][0] += xr[r] * wb.x; accB[r][1] += xr[r] * wb.y;
            accB[r][2] += xr[r] * wb.z; accB[r][3] += xr[r] * wb.w;
        }
    }

    #pragma unroll
    for (int r = 0; r < 4; r++) {
        int row = base + ty * 4 + r;
        float4 hA = make_float4(accA[r][0], accA[r][1], accA[r][2], accA[r][3]);
        float4 hB = make_float4(accB[r][0], accB[r][1], accB[r][2], accB[r][3]);
        if (row < N) {
            uint4 pk;
            pk.x = h2_to_u(__floats2half2_rn(hA.x, hA.y));
            pk.y = h2_to_u(__floats2half2_rn(hA.z, hA.w));
            pk.z = h2_to_u(__floats2half2_rn(hB.x, hB.y));
            pk.w = h2_to_u(__floats2half2_rn(hB.z, hB.w));
            *(uint4*)&g_h2h[row * 128 + tx * 8] = pk;
        }
        float p = hA.x * asA.x + hA.y * asA.y + hA.z * asA.z + hA.w * asA.w
                + hB.x * asB.x + hB.y * asB.y + hB.z * asB.z + hB.w * asB.w;
        float q = hA.x * adA.x + hA.y * adA.y + hA.z * adA.z + hA.w * adA.w
                + hB.x * adB.x + hB.y * adB.y + hB.z * adB.z + hB.w * adB.w;
        #pragma unroll
        for (int o = 1; o <= 8; o <<= 1) {
            p += __shfl_xor_sync(0xffffffffu, p, o);
            q += __shfl_xor_sync(0xffffffffu, q, o);
        }
        if (tx == 0 && row < N) { g_as2[row] = p; g_ad2[row] = q; }
    }
}

// ---------------- Layer2 aggregation: warp per dst node, fp16 gather, single sweep ----------------
__global__ void k_agg2(const float* __restrict__ b2, int N, float* __restrict__ out) {
    int node = blockIdx.x * 8 + (threadIdx.x >> 5);
    if (node >= N) return;
    int lane = threadIdx.x & 31;
    int start = g_rowptr[node], end = g_rowptr[node + 1];
    float ad = g_ad2[node];
    float4 acc = make_float4(0.f, 0.f, 0.f, 0.f);
    float ssum = 0.f;
    #pragma unroll 4
    for (int i = start; i < end; i++) {
        int src = g_csr[i];
        float ex = __expf(lrelu(g_as2[src] + ad));
        ssum += ex;
        uint2 pk = *(const uint2*)&g_h2h[src * 128 + lane * 4];  // 4 halves
        float2 v0 = __half22float2(u_to_h2(pk.x));
        float2 v1 = __half22float2(u_to_h2(pk.y));
        acc.x += ex * v0.x; acc.y += ex * v0.y;
        acc.z += ex * v1.x; acc.w += ex * v1.y;
    }
    float inv = 1.f / ssum;
    float4 bb = ((const float4*)b2)[lane];
    float4 o;
    o.x = acc.x * inv + bb.x;
    o.y = acc.y * inv + bb.y;
    o.z = acc.z * inv + bb.z;
    o.w = acc.w * inv + bb.w;
    ((float4*)out)[node * 32 + lane] = o;
}

// ---------------- launch ----------------
extern "C" void kernel_launch(void* const* d_in, const int* in_sizes, int n_in,
                              void* d_out, int out_size) {
    const float* x   = (const float*)d_in[0];
    const void*  ei  = d_in[1];
    const float* W1  = (const float*)d_in[2];
    const float* as1 = (const float*)d_in[3];
    const float* ad1 = (const float*)d_in[4];
    const float* b1  = (const float*)d_in[5];
    const float* W2  = (const float*)d_in[6];
    const float* as2 = (const float*)d_in[7];
    const float* ad2 = (const float*)d_in[8];
    const float* b2  = (const float*)d_in[9];
    float* out = (float*)d_out;

    int N = in_sizes[0] / 128;
    int E = in_sizes[1] / 2;

    k_init_deg<<<(N + 255) / 256, 256>>>(ei, N);
    k_count<<<(E + 255) / 256, 256>>>(ei, E, N);
    int nb = (N + 1023) / 1024;
    k_scan1<<<nb, 1024>>>(N);
    k_scan3<<<nb, 1024>>>(N, E + N);   // covers N+1 entries (nb*1024 >= N+1)
    k_fill<<<(E + N + 255) / 256, 256>>>(ei, E, N);
    int ng = (N + 63) / 64;
    k_gemm1<<<ng, 256>>>(x, W1, as1, ad1, N);
    k_agg1<<<(N + 7) / 8, 256>>>(b1, N);
    k_gemm2<<<ng, 256>>>(W2, as2, ad2, N);
    k_agg2<<<(N + 7) / 8, 256>>>(b2, N, out);
}

// round 10
// speedup vs baseline: 1.3258x; 1.0239x over previous
#include <cuda_runtime.h>
#include <cuda_fp16.h>
#include <math_constants.h>

// Problem dims fixed by setup_inputs(): N=100000, E=1600000, Fin=128, H1=2, Fh=32, Fout=128
#define NN 100000
#define EE 1600000
#define ET (EE + NN)

// ---------------- scratch (static device memory; no allocations allowed) ----------------
__device__ int   g_is64;
__device__ int   g_deg[NN];
__device__ int   g_rowptr[NN + 1];
__device__ int   g_cursor[NN];
__device__ int   g_blksum[128];
__device__ int   g_csr[ET];
__device__ __align__(16) __half g_h1h[NN * 64];   // layer1 pre-agg features (fp16 gather table)
__device__ float g_as1[NN * 2];                   // alpha_src layer1 [N,H1]
__device__ float g_ad1[NN * 2];                   // alpha_dst layer1
__device__ __align__(16) float  g_h1p[NN * 64];   // relu(layer1 out), fp32 (linear reads in gemm2)
__device__ __align__(16) __half g_h2h[NN * 128];  // layer2 pre-agg features (fp16 gather table)
__device__ float g_as2[NN];
__device__ float g_ad2[NN];

__device__ __forceinline__ float lrelu(float x) { return x > 0.f ? x : 0.2f * x; }

__device__ __forceinline__ unsigned h2_to_u(__half2 h) {
    union { __half2 h; unsigned u; } c; c.h = h; return c.u;
}
__device__ __forceinline__ __half2 u_to_h2(unsigned u) {
    union { __half2 h; unsigned u; } c; c.u = u; return c.h;
}

// ---------------- CSR build ----------------
// edge_index may arrive as int64 (reference dtype) or narrowed to int32 by the
// harness. Probe once: int32 data read as int64 fuses two node indices ->
// value >= N with overwhelming probability.
__global__ void k_init_deg(const void* ei, int N) {
    int i = blockIdx.x * blockDim.x + threadIdx.x;
    if (i < N) g_deg[i] = 1;  // self-loop
    if (i == 0) {             // dtype probe (visible to later kernels at launch boundary)
        const long long* p = (const long long*)ei;
        int ok = 1;
        #pragma unroll
        for (int k = 0; k < 16; k++) {
            long long v = p[k];
            if (v < 0 || v >= (long long)N) { ok = 0; break; }
        }
        g_is64 = ok;
    }
}

// 4 edges per thread (dst only). E is divisible by 4 (1.6M); guard handles the general case.
__global__ void k_count(const void* __restrict__ ei, int E, int N) {
    int i = blockIdx.x * blockDim.x + threadIdx.x;
    int e = i * 4;
    if (e >= E) return;
    int d[4];
    if (g_is64) {
        const long long* p = (const long long*)ei + E;
        longlong4 v = *(const longlong4*)&p[e];
        d[0] = (int)v.x; d[1] = (int)v.y; d[2] = (int)v.z; d[3] = (int)v.w;
    } else {
        const int* p = (const int*)ei + E;
        int4 v = *(const int4*)&p[e];
        d[0] = v.x; d[1] = v.y; d[2] = v.z; d[3] = v.w;
    }
    #pragma unroll
    for (int k = 0; k < 4; k++)
        if (e + k < E && (unsigned)d[k] < (unsigned)N) atomicAdd(&g_deg[d[k]], 1);
}

__global__ void k_scan1(int N) {
    __shared__ int sm[1024];
    int idx = blockIdx.x * 1024 + threadIdx.x;
    int v = (idx < N) ? g_deg[idx] : 0;
    sm[threadIdx.x] = v;
    __syncthreads();
    #pragma unroll
    for (int off = 1; off < 1024; off <<= 1) {
        int t = (threadIdx.x >= off) ? sm[threadIdx.x - off] : 0;
        __syncthreads();
        sm[threadIdx.x] += t;
        __syncthreads();
    }
    if (idx < N) g_rowptr[idx] = sm[threadIdx.x] - v;  // exclusive
    if (threadIdx.x == 1023) g_blksum[blockIdx.x] = sm[1023];
}

// scan3 with inline block-sum prefix: each block reduces blksum[0..b-1] itself (<=98 values)
__global__ void k_scan3(int N, int total) {
    __shared__ int ws[4];
    __shared__ int sh_prefix;
    int b = blockIdx.x;
    int t = threadIdx.x;
    if (t < 128) {
        int lane = t & 31, w = t >> 5;
        int v = (t < b) ? g_blksum[t] : 0;   // b <= 97 < 128
        #pragma unroll
        for (int o = 16; o; o >>= 1) v += __shfl_xor_sync(0xffffffffu, v, o);
        if (lane == 0) ws[w] = v;
    }
    __syncthreads();
    if (t == 0) sh_prefix = ws[0] + ws[1] + ws[2] + ws[3];
    __syncthreads();
    int idx = b * 1024 + t;
    if (idx > N) return;
    if (idx == N) { g_rowptr[N] = total; return; }
    int v = g_rowptr[idx] + sh_prefix;
    g_rowptr[idx] = v;
    g_cursor[idx] = v;
}

// 4 edges per thread; self-loop range appended after the E/4 edge-quads.
__global__ void k_fill(const void* __restrict__ ei, int E, int N) {
    int i = blockIdx.x * blockDim.x + threadIdx.x;
    int E4 = (E + 3) >> 2;
    if (i < E4) {
        int e = i * 4;
        int s[4], d[4];
        if (g_is64) {
            const long long* ps = (const long long*)ei;
            const long long* pd = ps + E;
            longlong4 vs = *(const longlong4*)&ps[e];
            longlong4 vd = *(const longlong4*)&pd[e];
            s[0] = (int)vs.x; s[1] = (int)vs.y; s[2] = (int)vs.z; s[3] = (int)vs.w;
            d[0] = (int)vd.x; d[1] = (int)vd.y; d[2] = (int)vd.z; d[3] = (int)vd.w;
        } else {
            const int* ps = (const int*)ei;
            const int* pd = ps + E;
            int4 vs = *(const int4*)&ps[e];
            int4 vd = *(const int4*)&pd[e];
            s[0] = vs.x; s[1] = vs.y; s[2] = vs.z; s[3] = vs.w;
            d[0] = vd.x; d[1] = vd.y; d[2] = vd.z; d[3] = vd.w;
        }
        #pragma unroll
        for (int k = 0; k < 4; k++) {
            if (e + k >= E) break;
            if ((unsigned)d[k] >= (unsigned)N || (unsigned)s[k] >= (unsigned)N) continue;
            int pos = atomicAdd(&g_cursor[d[k]], 1);
            g_csr[pos] = s[k];
        }
    } else {
        int node = i - E4;
        if (node < N) {
            int pos = atomicAdd(&g_cursor[node], 1);
            g_csr[pos] = node;
        }
    }
}

// ---------------- GEMM1: h1 = x @ W1 [128x64] -> fp16 table, fused alpha epilogue ----------------
// Tile 64 rows x 64 cols. 256 threads; 4x4 register block per thread.
__global__ void __launch_bounds__(256) k_gemm1(const float* __restrict__ x,
                                               const float* __restrict__ W1,
                                               const float* __restrict__ as,
                                               const float* __restrict__ ad, int N) {
    __shared__ float xs[128 * 68];   // 34.8 KB, transposed x tile
    int t = threadIdx.x;
    int tx = t & 15;                 // cols tx*4 .. tx*4+3
    int ty = t >> 4;                 // rows ty*4 .. ty*4+3
    int head = tx >> 3;
    int base = blockIdx.x * 64;

    float4 as4 = ((const float4*)as)[tx];
    float4 ad4 = ((const float4*)ad)[tx];

    for (int i = t; i < 64 * 128; i += 256) {
        int row = i >> 7, k = i & 127;
        int r = base + row;
        xs[k * 68 + row] = (r < N) ? x[r * 128 + k] : 0.f;
    }
    __syncthreads();

    float acc[4][4] = {};
    #pragma unroll 4
    for (int k = 0; k < 128; k++) {
        float4 w = __ldg((const float4*)&W1[k * 64 + tx * 4]);
        float4 xv = *(const float4*)&xs[k * 68 + ty * 4];
        acc[0][0] += xv.x * w.x; acc[0][1] += xv.x * w.y; acc[0][2] += xv.x * w.z; acc[0][3] += xv.x * w.w;
        acc[1][0] += xv.y * w.x; acc[1][1] += xv.y * w.y; acc[1][2] += xv.y * w.z; acc[1][3] += xv.y * w.w;
        acc[2][0] += xv.z * w.x; acc[2][1] += xv.z * w.y; acc[2][2] += xv.z * w.z; acc[2][3] += xv.z * w.w;
        acc[3][0] += xv.w * w.x; acc[3][1] += xv.w * w.y; acc[3][2] += xv.w * w.z; acc[3][3] += xv.w * w.w;
    }

    #pragma unroll
    for (int r = 0; r < 4; r++) {
        int row = base + ty * 4 + r;
        float4 h = make_float4(acc[r][0], acc[r][1], acc[r][2], acc[r][3]);
        if (row < N) {
            uint2 pk;
            pk.x = h2_to_u(__floats2half2_rn(h.x, h.y));
            pk.y = h2_to_u(__floats2half2_rn(h.z, h.w));
            *(uint2*)&g_h1h[row * 64 + tx * 4] = pk;
        }
        float p = h.x * as4.x + h.y * as4.y + h.z * as4.z + h.w * as4.w;
        float q = h.x * ad4.x + h.y * ad4.y + h.z * ad4.z + h.w * ad4.w;
        #pragma unroll
        for (int o = 1; o <= 4; o <<= 1) {
            p += __shfl_xor_sync(0xffffffffu, p, o);
            q += __shfl_xor_sync(0xffffffffu, q, o);
        }
        if ((tx & 7) == 0 && row < N) {
            g_as1[row * 2 + head] = p;
            g_ad1[row * 2 + head] = q;
        }
    }
}

// ---------------- Layer1 aggregation: warp per dst node, fp16 gather, single sweep ----------------
// Lane l owns features {2l, 2l+1} (one half2). Lanes 0-15 -> head0, 16-31 -> head1.
__global__ void k_agg1(const float* __restrict__ b1, int N) {
    int node = blockIdx.x * 8 + (threadIdx.x >> 5);
    if (node >= N) return;
    int lane = threadIdx.x & 31;
    int hsel = lane >> 4;
    int start = g_rowptr[node], end = g_rowptr[node + 1];
    float adh = g_ad1[node * 2 + hsel];
    float2 acc = make_float2(0.f, 0.f);
    float ssum = 0.f;
    #pragma unroll 4
    for (int i = start; i < end; i++) {
        int src = g_csr[i];
        float a = g_as1[src * 2 + hsel];
        float ex = __expf(lrelu(a + adh));
        ssum += ex;
        float2 v = __half22float2(*(const __half2*)&g_h1h[src * 64 + lane * 2]);
        acc.x += ex * v.x; acc.y += ex * v.y;
    }
    float inv = 1.f / ssum;
    float2 bb = ((const float2*)b1)[lane];
    float2 o = make_float2(fmaxf(acc.x * inv + bb.x, 0.f), fmaxf(acc.y * inv + bb.y, 0.f));
    *(float2*)&g_h1p[node * 64 + lane * 2] = o;
}

// ---------------- GEMM2: h2 = h1p @ W2 [64x128] -> fp16 table, fused alpha2 ----------------
// Tile 64 rows x 128 cols. 256 threads; 4x8 register block per thread.
__global__ void __launch_bounds__(256) k_gemm2(const float* __restrict__ W2,
                                               const float* __restrict__ as,
                                               const float* __restrict__ ad, int N) {
    __shared__ float xs[64 * 68];    // 17.4 KB
    int t = threadIdx.x;
    int tx = t & 15;                 // cols tx*8 .. tx*8+7
    int ty = t >> 4;                 // rows ty*4 .. ty*4+3
    int base = blockIdx.x * 64;

    float4 asA = ((const float4*)as)[tx * 2], asB = ((const float4*)as)[tx * 2 + 1];
    float4 adA = ((const float4*)ad)[tx * 2], adB = ((const float4*)ad)[tx * 2 + 1];

    for (int i = t; i < 64 * 64; i += 256) {
        int row = i >> 6, k = i & 63;
        int r = base + row;
        xs[k * 68 + row] = (r < N) ? g_h1p[r * 64 + k] : 0.f;
    }
    __syncthreads();

    float accA[4][4] = {}, accB[4][4] = {};
    #pragma unroll 4
    for (int k = 0; k < 64; k++) {
        float4 wa = __ldg((const float4*)&W2[k * 128 + tx * 8]);
        float4 wb = __ldg((const float4*)&W2[k * 128 + tx * 8 + 4]);
        float4 xv = *(const float4*)&xs[k * 68 + ty * 4];
        float xr[4] = {xv.x, xv.y, xv.z, xv.w};
        #pragma unroll
        for (int r = 0; r < 4; r++) {
            accA[r][0] += xr[r] * wa.x; accA[r][1] += xr[r] * wa.y;
            accA[r][2] += xr[r] * wa.z; accA[r][3] += xr[r] * wa.w;
            accB[r][0] += xr[r] * wb.x; accB[r][1] += xr[r] * wb.y;
            accB[r][2] += xr[r] * wb.z; accB[r][3] += xr[r] * wb.w;
        }
    }

    #pragma unroll
    for (int r = 0; r < 4; r++) {
        int row = base + ty * 4 + r;
        float4 hA = make_float4(accA[r][0], accA[r][1], accA[r][2], accA[r][3]);
        float4 hB = make_float4(accB[r][0], accB[r][1], accB[r][2], accB[r][3]);
        if (row < N) {
            uint4 pk;
            pk.x = h2_to_u(__floats2half2_rn(hA.x, hA.y));
            pk.y = h2_to_u(__floats2half2_rn(hA.z, hA.w));
            pk.z = h2_to_u(__floats2half2_rn(hB.x, hB.y));
            pk.w = h2_to_u(__floats2half2_rn(hB.z, hB.w));
            *(uint4*)&g_h2h[row * 128 + tx * 8] = pk;
        }
        float p = hA.x * asA.x + hA.y * asA.y + hA.z * asA.z + hA.w * asA.w
                + hB.x * asB.x + hB.y * asB.y + hB.z * asB.z + hB.w * asB.w;
        float q = hA.x * adA.x + hA.y * adA.y + hA.z * adA.z + hA.w * adA.w
                + hB.x * adB.x + hB.y * adB.y + hB.z * adB.z + hB.w * adB.w;
        #pragma unroll
        for (int o = 1; o <= 8; o <<= 1) {
            p += __shfl_xor_sync(0xffffffffu, p, o);
            q += __shfl_xor_sync(0xffffffffu, q, o);
        }
        if (tx == 0 && row < N) { g_as2[row] = p; g_ad2[row] = q; }
    }
}

// ---------------- Layer2 aggregation: warp per dst node, fp16 gather, single sweep ----------------
__global__ void k_agg2(const float* __restrict__ b2, int N, float* __restrict__ out) {
    int node = blockIdx.x * 8 + (threadIdx.x >> 5);
    if (node >= N) return;
    int lane = threadIdx.x & 31;
    int start = g_rowptr[node], end = g_rowptr[node + 1];
    float ad = g_ad2[node];
    float4 acc = make_float4(0.f, 0.f, 0.f, 0.f);
    float ssum = 0.f;
    #pragma unroll 4
    for (int i = start; i < end; i++) {
        int src = g_csr[i];
        float ex = __expf(lrelu(g_as2[src] + ad));
        ssum += ex;
        uint2 pk = *(const uint2*)&g_h2h[src * 128 + lane * 4];  // 4 halves
        float2 v0 = __half22float2(u_to_h2(pk.x));
        float2 v1 = __half22float2(u_to_h2(pk.y));
        acc.x += ex * v0.x; acc.y += ex * v0.y;
        acc.z += ex * v1.x; acc.w += ex * v1.y;
    }
    float inv = 1.f / ssum;
    float4 bb = ((const float4*)b2)[lane];
    float4 o;
    o.x = acc.x * inv + bb.x;
    o.y = acc.y * inv + bb.y;
    o.z = acc.z * inv + bb.z;
    o.w = acc.w * inv + bb.w;
    ((float4*)out)[node * 32 + lane] = o;
}

// ---------------- launch: fork CSR build onto a side stream, overlap with GEMM1 ----------------
extern "C" void kernel_launch(void* const* d_in, const int* in_sizes, int n_in,
                              void* d_out, int out_size) {
    const float* x   = (const float*)d_in[0];
    const void*  ei  = d_in[1];
    const float* W1  = (const float*)d_in[2];
    const float* as1 = (const float*)d_in[3];
    const float* ad1 = (const float*)d_in[4];
    const float* b1  = (const float*)d_in[5];
    const float* W2  = (const float*)d_in[6];
    const float* as2 = (const float*)d_in[7];
    const float* ad2 = (const float*)d_in[8];
    const float* b2  = (const float*)d_in[9];
    float* out = (float*)d_out;

    int N = in_sizes[0] / 128;
    int E = in_sizes[1] / 2;

    static cudaStream_t s2 = nullptr;
    static cudaEvent_t evFork = nullptr, evJoin = nullptr;
    if (!s2) {
        cudaStreamCreateWithFlags(&s2, cudaStreamNonBlocking);
        cudaEventCreateWithFlags(&evFork, cudaEventDisableTiming);
        cudaEventCreateWithFlags(&evJoin, cudaEventDisableTiming);
    }

    // fork: CSR build on s2
    cudaEventRecord(evFork, 0);
    cudaStreamWaitEvent(s2, evFork, 0);
    k_init_deg<<<(N + 255) / 256, 256, 0, s2>>>(ei, N);
    k_count<<<(E / 4 + 255) / 256, 256, 0, s2>>>(ei, E, N);
    int nb = (N + 1023) / 1024;
    k_scan1<<<nb, 1024, 0, s2>>>(N);
    k_scan3<<<nb, 1024, 0, s2>>>(N, E + N);
    {
        int E4 = (E + 3) / 4;
        k_fill<<<(E4 + N + 255) / 256, 256, 0, s2>>>(ei, E, N);
    }
    cudaEventRecord(evJoin, s2);

    // concurrent: GEMM1 on the main (capture) stream
    int ng = (N + 63) / 64;
    k_gemm1<<<ng, 256>>>(x, W1, as1, ad1, N);

    // join, then the dependent tail
    cudaStreamWaitEvent(0, evJoin, 0);
    k_agg1<<<(N + 7) / 8, 256>>>(b1, N);
    k_gemm2<<<ng, 256>>>(W2, as2, ad2, N);
    k_agg2<<<(N + 7) / 8, 256>>>(b2, N, out);
}

// round 11
// speedup vs baseline: 1.3409x; 1.0113x over previous
#include <cuda_runtime.h>
#include <cuda_fp16.h>
#include <math_constants.h>

// Problem dims fixed by setup_inputs(): N=100000, E=1600000, Fin=128, H1=2, Fh=32, Fout=128
#define NN 100000
#define EE 1600000
#define ET (EE + NN)

// ---------------- scratch (static device memory; no allocations allowed) ----------------
__device__ int   g_is64;
__device__ int   g_deg[NN];
__device__ int   g_rowptr[NN + 1];
__device__ int   g_cursor[NN];
__device__ int   g_blksum[128];
__device__ int   g_csr[ET];
__device__ __align__(16) __half g_h1h[NN * 64];   // layer1 pre-agg features (fp16 gather table)
__device__ __align__(8) float g_as1[NN * 2];      // alpha_src layer1 [N,H1]
__device__ __align__(8) float g_ad1[NN * 2];      // alpha_dst layer1
__device__ __align__(16) float  g_h1p[NN * 64];   // relu(layer1 out), fp32 (linear reads in gemm2)
__device__ __align__(16) __half g_h2h[NN * 128];  // layer2 pre-agg features (fp16 gather table)
__device__ float g_as2[NN];
__device__ float g_ad2[NN];

__device__ __forceinline__ float lrelu(float x) { return x > 0.f ? x : 0.2f * x; }

__device__ __forceinline__ float wsum(float v) {
    #pragma unroll
    for (int o = 16; o; o >>= 1) v += __shfl_xor_sync(0xffffffffu, v, o);
    return v;
}

__device__ __forceinline__ unsigned h2_to_u(__half2 h) {
    union { __half2 h; unsigned u; } c; c.h = h; return c.u;
}
__device__ __forceinline__ __half2 u_to_h2(unsigned u) {
    union { __half2 h; unsigned u; } c; c.u = u; return c.h;
}

// ---------------- CSR build ----------------
// edge_index may arrive as int64 (reference dtype) or narrowed to int32 by the
// harness. Probe once: int32 data read as int64 fuses two node indices ->
// value >= N with overwhelming probability.
__global__ void k_init_deg(const void* ei, int N) {
    int i = blockIdx.x * blockDim.x + threadIdx.x;
    if (i < N) g_deg[i] = 1;  // self-loop
    if (i == 0) {
        const long long* p = (const long long*)ei;
        int ok = 1;
        #pragma unroll
        for (int k = 0; k < 16; k++) {
            long long v = p[k];
            if (v < 0 || v >= (long long)N) { ok = 0; break; }
        }
        g_is64 = ok;
    }
}

__global__ void k_count(const void* __restrict__ ei, int E, int N) {
    int i = blockIdx.x * blockDim.x + threadIdx.x;
    int e = i * 4;
    if (e >= E) return;
    int d[4];
    if (g_is64) {
        const long long* p = (const long long*)ei + E;
        longlong4 v = *(const longlong4*)&p[e];
        d[0] = (int)v.x; d[1] = (int)v.y; d[2] = (int)v.z; d[3] = (int)v.w;
    } else {
        const int* p = (const int*)ei + E;
        int4 v = *(const int4*)&p[e];
        d[0] = v.x; d[1] = v.y; d[2] = v.z; d[3] = v.w;
    }
    #pragma unroll
    for (int k = 0; k < 4; k++)
        if (e + k < E && (unsigned)d[k] < (unsigned)N) atomicAdd(&g_deg[d[k]], 1);
}

__global__ void k_scan1(int N) {
    __shared__ int sm[1024];
    int idx = blockIdx.x * 1024 + threadIdx.x;
    int v = (idx < N) ? g_deg[idx] : 0;
    sm[threadIdx.x] = v;
    __syncthreads();
    #pragma unroll
    for (int off = 1; off < 1024; off <<= 1) {
        int t = (threadIdx.x >= off) ? sm[threadIdx.x - off] : 0;
        __syncthreads();
        sm[threadIdx.x] += t;
        __syncthreads();
    }
    if (idx < N) g_rowptr[idx] = sm[threadIdx.x] - v;  // exclusive
    if (threadIdx.x == 1023) g_blksum[blockIdx.x] = sm[1023];
}

// scan3 with inline block-sum prefix: each block reduces blksum[0..b-1] itself (<=98 values)
__global__ void k_scan3(int N, int total) {
    __shared__ int ws[4];
    __shared__ int sh_prefix;
    int b = blockIdx.x;
    int t = threadIdx.x;
    if (t < 128) {
        int lane = t & 31, w = t >> 5;
        int v = (t < b) ? g_blksum[t] : 0;   // b <= 97 < 128
        #pragma unroll
        for (int o = 16; o; o >>= 1) v += __shfl_xor_sync(0xffffffffu, v, o);
        if (lane == 0) ws[w] = v;
    }
    __syncthreads();
    if (t == 0) sh_prefix = ws[0] + ws[1] + ws[2] + ws[3];
    __syncthreads();
    int idx = b * 1024 + t;
    if (idx > N) return;
    if (idx == N) { g_rowptr[N] = total; return; }
    int v = g_rowptr[idx] + sh_prefix;
    g_rowptr[idx] = v;
    g_cursor[idx] = v;
}

__global__ void k_fill(const void* __restrict__ ei, int E, int N) {
    int i = blockIdx.x * blockDim.x + threadIdx.x;
    int E4 = (E + 3) >> 2;
    if (i < E4) {
        int e = i * 4;
        int s[4], d[4];
        if (g_is64) {
            const long long* ps = (const long long*)ei;
            const long long* pd = ps + E;
            longlong4 vs = *(const longlong4*)&ps[e];
            longlong4 vd = *(const longlong4*)&pd[e];
            s[0] = (int)vs.x; s[1] = (int)vs.y; s[2] = (int)vs.z; s[3] = (int)vs.w;
            d[0] = (int)vd.x; d[1] = (int)vd.y; d[2] = (int)vd.z; d[3] = (int)vd.w;
        } else {
            const int* ps = (const int*)ei;
            const int* pd = ps + E;
            int4 vs = *(const int4*)&ps[e];
            int4 vd = *(const int4*)&pd[e];
            s[0] = vs.x; s[1] = vs.y; s[2] = vs.z; s[3] = vs.w;
            d[0] = vd.x; d[1] = vd.y; d[2] = vd.z; d[3] = vd.w;
        }
        #pragma unroll
        for (int k = 0; k < 4; k++) {
            if (e + k >= E) break;
            if ((unsigned)d[k] >= (unsigned)N || (unsigned)s[k] >= (unsigned)N) continue;
            int pos = atomicAdd(&g_cursor[d[k]], 1);
            g_csr[pos] = s[k];
        }
    } else {
        int node = i - E4;
        if (node < N) {
            int pos = atomicAdd(&g_cursor[node], 1);
            g_csr[pos] = node;
        }
    }
}

// ---------------- GEMM1: h1 = x @ W1 [128x64] -> fp16 table, fused alpha epilogue ----------------
__global__ void __launch_bounds__(256) k_gemm1(const float* __restrict__ x,
                                               const float* __restrict__ W1,
                                               const float* __restrict__ as,
                                               const float* __restrict__ ad, int N) {
    __shared__ float xs[128 * 68];   // 34.8 KB, transposed x tile
    int t = threadIdx.x;
    int tx = t & 15;                 // cols tx*4 .. tx*4+3
    int ty = t >> 4;                 // rows ty*4 .. ty*4+3
    int head = tx >> 3;
    int base = blockIdx.x * 64;

    float4 as4 = ((const float4*)as)[tx];
    float4 ad4 = ((const float4*)ad)[tx];

    for (int i = t; i < 64 * 128; i += 256) {
        int row = i >> 7, k = i & 127;
        int r = base + row;
        xs[k * 68 + row] = (r < N) ? x[r * 128 + k] : 0.f;
    }
    __syncthreads();

    float acc[4][4] = {};
    #pragma unroll 4
    for (int k = 0; k < 128; k++) {
        float4 w = __ldg((const float4*)&W1[k * 64 + tx * 4]);
        float4 xv = *(const float4*)&xs[k * 68 + ty * 4];
        acc[0][0] += xv.x * w.x; acc[0][1] += xv.x * w.y; acc[0][2] += xv.x * w.z; acc[0][3] += xv.x * w.w;
        acc[1][0] += xv.y * w.x; acc[1][1] += xv.y * w.y; acc[1][2] += xv.y * w.z; acc[1][3] += xv.y * w.w;
        acc[2][0] += xv.z * w.x; acc[2][1] += xv.z * w.y; acc[2][2] += xv.z * w.z; acc[2][3] += xv.z * w.w;
        acc[3][0] += xv.w * w.x; acc[3][1] += xv.w * w.y; acc[3][2] += xv.w * w.z; acc[3][3] += xv.w * w.w;
    }

    #pragma unroll
    for (int r = 0; r < 4; r++) {
        int row = base + ty * 4 + r;
        float4 h = make_float4(acc[r][0], acc[r][1], acc[r][2], acc[r][3]);
        if (row < N) {
            uint2 pk;
            pk.x = h2_to_u(__floats2half2_rn(h.x, h.y));
            pk.y = h2_to_u(__floats2half2_rn(h.z, h.w));
            *(uint2*)&g_h1h[row * 64 + tx * 4] = pk;
        }
        float p = h.x * as4.x + h.y * as4.y + h.z * as4.z + h.w * as4.w;
        float q = h.x * ad4.x + h.y * ad4.y + h.z * ad4.z + h.w * ad4.w;
        #pragma unroll
        for (int o = 1; o <= 4; o <<= 1) {
            p += __shfl_xor_sync(0xffffffffu, p, o);
            q += __shfl_xor_sync(0xffffffffu, q, o);
        }
        if ((tx & 7) == 0 && row < N) {
            g_as1[row * 2 + head] = p;
            g_ad1[row * 2 + head] = q;
        }
    }
}

// ---------------- Layer1 aggregation: warp-cooperative two-phase ----------------
// Phase A: lane j computes (src, ex0, ex1) for edge base+j in parallel.
// Phase B: broadcast via shfl; lane l gathers its half2 features (lanes 0-15 head0, 16-31 head1).
__global__ void k_agg1(const float* __restrict__ b1, int N) {
    int node = blockIdx.x * 8 + (threadIdx.x >> 5);
    if (node >= N) return;
    int lane = threadIdx.x & 31;
    int hsel = lane >> 4;
    int start = g_rowptr[node], end = g_rowptr[node + 1];
    float2 adp = *(const float2*)&g_ad1[node * 2];
    float2 acc = make_float2(0.f, 0.f);
    float s0 = 0.f, s1 = 0.f;
    for (int b = start; b < end; b += 32) {
        int i = b + lane;
        int src_l = 0; float ex0_l = 0.f, ex1_l = 0.f;
        if (i < end) {
            src_l = g_csr[i];
            float2 a = *(const float2*)&g_as1[src_l * 2];
            ex0_l = __expf(lrelu(a.x + adp.x));
            ex1_l = __expf(lrelu(a.y + adp.y));
        }
        s0 += ex0_l; s1 += ex1_l;
        int cnt = min(32, end - b);
        #pragma unroll 4
        for (int j = 0; j < cnt; j++) {
            int src  = __shfl_sync(0xffffffffu, src_l, j);
            float e0 = __shfl_sync(0xffffffffu, ex0_l, j);
            float e1 = __shfl_sync(0xffffffffu, ex1_l, j);
            float exh = hsel ? e1 : e0;
            float2 v = __half22float2(*(const __half2*)&g_h1h[src * 64 + lane * 2]);
            acc.x += exh * v.x; acc.y += exh * v.y;
        }
    }
    s0 = wsum(s0); s1 = wsum(s1);
    float inv = 1.f / (hsel ? s1 : s0);
    float2 bb = ((const float2*)b1)[lane];
    float2 o = make_float2(fmaxf(acc.x * inv + bb.x, 0.f), fmaxf(acc.y * inv + bb.y, 0.f));
    *(float2*)&g_h1p[node * 64 + lane * 2] = o;
}

// ---------------- GEMM2: h2 = h1p @ W2 [64x128] -> fp16 table, fused alpha2 ----------------
__global__ void __launch_bounds__(256) k_gemm2(const float* __restrict__ W2,
                                               const float* __restrict__ as,
                                               const float* __restrict__ ad, int N) {
    __shared__ float xs[64 * 68];    // 17.4 KB
    int t = threadIdx.x;
    int tx = t & 15;                 // cols tx*8 .. tx*8+7
    int ty = t >> 4;                 // rows ty*4 .. ty*4+3
    int base = blockIdx.x * 64;

    float4 asA = ((const float4*)as)[tx * 2], asB = ((const float4*)as)[tx * 2 + 1];
    float4 adA = ((const float4*)ad)[tx * 2], adB = ((const float4*)ad)[tx * 2 + 1];

    for (int i = t; i < 64 * 64; i += 256) {
        int row = i >> 6, k = i & 63;
        int r = base + row;
        xs[k * 68 + row] = (r < N) ? g_h1p[r * 64 + k] : 0.f;
    }
    __syncthreads();

    float accA[4][4] = {}, accB[4][4] = {};
    #pragma unroll 4
    for (int k = 0; k < 64; k++) {
        float4 wa = __ldg((const float4*)&W2[k * 128 + tx * 8]);
        float4 wb = __ldg((const float4*)&W2[k * 128 + tx * 8 + 4]);
        float4 xv = *(const float4*)&xs[k * 68 + ty * 4];
        float xr[4] = {xv.x, xv.y, xv.z, xv.w};
        #pragma unroll
        for (int r = 0; r < 4; r++) {
            accA[r][0] += xr[r] * wa.x; accA[r][1] += xr[r] * wa.y;
            accA[r][2] += xr[r] * wa.z; accA[r][3] += xr[r] * wa.w;
            accB[r][0] += xr[r] * wb.x; accB[r][1] += xr[r] * wb.y;
            accB[r][2] += xr[r] * wb.z; accB[r][3] += xr[r] * wb.w;
        }
    }

    #pragma unroll
    for (int r = 0; r < 4; r++) {
        int row = base + ty * 4 + r;
        float4 hA = make_float4(accA[r][0], accA[r][1], accA[r][2], accA[r][3]);
        float4 hB = make_float4(accB[r][0], accB[r][1], accB[r][2], accB[r][3]);
        if (row < N) {
            uint4 pk;
            pk.x = h2_to_u(__floats2half2_rn(hA.x, hA.y));
            pk.y = h2_to_u(__floats2half2_rn(hA.z, hA.w));
            pk.z = h2_to_u(__floats2half2_rn(hB.x, hB.y));
            pk.w = h2_to_u(__floats2half2_rn(hB.z, hB.w));
            *(uint4*)&g_h2h[row * 128 + tx * 8] = pk;
        }
        float p = hA.x * asA.x + hA.y * asA.y + hA.z * asA.z + hA.w * asA.w
                + hB.x * asB.x + hB.y * asB.y + hB.z * asB.z + hB.w * asB.w;
        float q = hA.x * adA.x + hA.y * adA.y + hA.z * adA.z + hA.w * adA.w
                + hB.x * adB.x + hB.y * adB.y + hB.z * adB.z + hB.w * adB.w;
        #pragma unroll
        for (int o = 1; o <= 8; o <<= 1) {
            p += __shfl_xor_sync(0xffffffffu, p, o);
            q += __shfl_xor_sync(0xffffffffu, q, o);
        }
        if (tx == 0 && row < N) { g_as2[row] = p; g_ad2[row] = q; }
    }
}

// ---------------- Layer2 aggregation: warp-cooperative two-phase, fp16 gather ----------------
__global__ void k_agg2(const float* __restrict__ b2, int N, float* __restrict__ out) {
    int node = blockIdx.x * 8 + (threadIdx.x >> 5);
    if (node >= N) return;
    int lane = threadIdx.x & 31;
    int start = g_rowptr[node], end = g_rowptr[node + 1];
    float ad = g_ad2[node];
    float4 acc = make_float4(0.f, 0.f, 0.f, 0.f);
    float spart = 0.f;
    for (int b = start; b < end; b += 32) {
        int i = b + lane;
        int src_l = 0; float ex_l = 0.f;
        if (i < end) {
            src_l = g_csr[i];
            ex_l = __expf(lrelu(g_as2[src_l] + ad));
        }
        spart += ex_l;
        int cnt = min(32, end - b);
        #pragma unroll 4
        for (int j = 0; j < cnt; j++) {
            int src  = __shfl_sync(0xffffffffu, src_l, j);
            float ex = __shfl_sync(0xffffffffu, ex_l, j);
            uint2 pk = *(const uint2*)&g_h2h[src * 128 + lane * 4];
            float2 v0 = __half22float2(u_to_h2(pk.x));
            float2 v1 = __half22float2(u_to_h2(pk.y));
            acc.x += ex * v0.x; acc.y += ex * v0.y;
            acc.z += ex * v1.x; acc.w += ex * v1.y;
        }
    }
    float inv = 1.f / wsum(spart);
    float4 bb = ((const float4*)b2)[lane];
    float4 o;
    o.x = acc.x * inv + bb.x;
    o.y = acc.y * inv + bb.y;
    o.z = acc.z * inv + bb.z;
    o.w = acc.w * inv + bb.w;
    ((float4*)out)[node * 32 + lane] = o;
}

// ---------------- launch: fork CSR build onto a side stream, overlap with GEMM1 ----------------
extern "C" void kernel_launch(void* const* d_in, const int* in_sizes, int n_in,
                              void* d_out, int out_size) {
    const float* x   = (const float*)d_in[0];
    const void*  ei  = d_in[1];
    const float* W1  = (const float*)d_in[2];
    const float* as1 = (const float*)d_in[3];
    const float* ad1 = (const float*)d_in[4];
    const float* b1  = (const float*)d_in[5];
    const float* W2  = (const float*)d_in[6];
    const float* as2 = (const float*)d_in[7];
    const float* ad2 = (const float*)d_in[8];
    const float* b2  = (const float*)d_in[9];
    float* out = (float*)d_out;

    int N = in_sizes[0] / 128;
    int E = in_sizes[1] / 2;

    static cudaStream_t s2 = nullptr;
    static cudaEvent_t evFork = nullptr, evJoin = nullptr;
    if (!s2) {
        cudaStreamCreateWithFlags(&s2, cudaStreamNonBlocking);
        cudaEventCreateWithFlags(&evFork, cudaEventDisableTiming);
        cudaEventCreateWithFlags(&evJoin, cudaEventDisableTiming);
    }

    // fork: CSR build on s2
    cudaEventRecord(evFork, 0);
    cudaStreamWaitEvent(s2, evFork, 0);
    k_init_deg<<<(N + 255) / 256, 256, 0, s2>>>(ei, N);
    k_count<<<(E / 4 + 255) / 256, 256, 0, s2>>>(ei, E, N);
    int nb = (N + 1023) / 1024;
    k_scan1<<<nb, 1024, 0, s2>>>(N);
    k_scan3<<<nb, 1024, 0, s2>>>(N, E + N);
    {
        int E4 = (E + 3) / 4;
        k_fill<<<(E4 + N + 255) / 256, 256, 0, s2>>>(ei, E, N);
    }
    cudaEventRecord(evJoin, s2);

    // concurrent: GEMM1 on the main (capture) stream
    int ng = (N + 63) / 64;
    k_gemm1<<<ng, 256>>>(x, W1, as1, ad1, N);

    // join, then the dependent tail
    cudaStreamWaitEvent(0, evJoin, 0);
    k_agg1<<<(N + 7) / 8, 256>>>(b1, N);
    k_gemm2<<<ng, 256>>>(W2, as2, ad2, N);
    k_agg2<<<(N + 7) / 8, 256>>>(b2, N, out);
}

// round 12
// speedup vs baseline: 1.4519x; 1.0828x over previous
#include <cuda_runtime.h>
#include <cuda_fp16.h>
#include <math_constants.h>

// Problem dims fixed by setup_inputs(): N=100000, E=1600000, Fin=128, H1=2, Fh=32, Fout=128
#define NN 100000
#define EE 1600000
#define ET (EE + NN)

// ---------------- scratch (static device memory; no allocations allowed) ----------------
__device__ int   g_is64;
__device__ int   g_deg[NN];
__device__ int   g_rowptr[NN + 1];
__device__ int   g_cursor[NN];
__device__ int   g_blksum[128];
__device__ int   g_csr[ET];
__device__ __align__(16) __half g_h1h[NN * 64];   // layer1 pre-agg features (fp16 gather table)
__device__ __align__(8) float g_as1[NN * 2];      // alpha_src layer1 [N,H1]
__device__ __align__(8) float g_ad1[NN * 2];      // alpha_dst layer1
__device__ __align__(16) float  g_h1p[NN * 64];   // relu(layer1 out), fp32 (linear reads in gemm2)
__device__ __align__(16) __half g_h2h[NN * 128];  // layer2 pre-agg features (fp16 gather table)
__device__ float g_as2[NN];
__device__ float g_ad2[NN];

__device__ __forceinline__ float lrelu(float x) { return x > 0.f ? x : 0.2f * x; }

__device__ __forceinline__ float wsum(float v) {
    #pragma unroll
    for (int o = 16; o; o >>= 1) v += __shfl_xor_sync(0xffffffffu, v, o);
    return v;
}

__device__ __forceinline__ unsigned h2_to_u(__half2 h) {
    union { __half2 h; unsigned u; } c; c.h = h; return c.u;
}
__device__ __forceinline__ __half2 u_to_h2(unsigned u) {
    union { __half2 h; unsigned u; } c; c.u = u; return c.h;
}

// ---- packed f32x2 helpers (Blackwell sm_100a: fma.rn.f32x2 = 2 IEEE fp32 FMAs / instr) ----
__device__ __forceinline__ unsigned long long pk2(float lo, float hi) {
    unsigned long long r;
    asm("mov.b64 %0, {%1, %2};" : "=l"(r) : "f"(lo), "f"(hi));
    return r;
}
__device__ __forceinline__ unsigned long long dup2(float v) {
    unsigned long long r;
    asm("mov.b64 %0, {%1, %1};" : "=l"(r) : "f"(v));
    return r;
}
__device__ __forceinline__ void fma2(unsigned long long& acc, unsigned long long a, unsigned long long b) {
    asm("fma.rn.f32x2 %0, %1, %2, %0;" : "+l"(acc) : "l"(a), "l"(b));
}
__device__ __forceinline__ float2 unpk2(unsigned long long v) {
    float lo, hi;
    asm("mov.b64 {%0, %1}, %2;" : "=f"(lo), "=f"(hi) : "l"(v));
    return make_float2(lo, hi);
}

// ---------------- CSR build ----------------
// edge_index may arrive as int64 (reference dtype) or narrowed to int32 by the
// harness. Probe once: int32 data read as int64 fuses two node indices ->
// value >= N with overwhelming probability.
__global__ void k_init_deg(const void* ei, int N) {
    int i = blockIdx.x * blockDim.x + threadIdx.x;
    if (i < N) g_deg[i] = 1;  // self-loop
    if (i == 0) {
        const long long* p = (const long long*)ei;
        int ok = 1;
        #pragma unroll
        for (int k = 0; k < 16; k++) {
            long long v = p[k];
            if (v < 0 || v >= (long long)N) { ok = 0; break; }
        }
        g_is64 = ok;
    }
}

__global__ void k_count(const void* __restrict__ ei, int E, int N) {
    int i = blockIdx.x * blockDim.x + threadIdx.x;
    int e = i * 4;
    if (e >= E) return;
    int d[4];
    if (g_is64) {
        const long long* p = (const long long*)ei + E;
        longlong4 v = *(const longlong4*)&p[e];
        d[0] = (int)v.x; d[1] = (int)v.y; d[2] = (int)v.z; d[3] = (int)v.w;
    } else {
        const int* p = (const int*)ei + E;
        int4 v = *(const int4*)&p[e];
        d[0] = v.x; d[1] = v.y; d[2] = v.z; d[3] = v.w;
    }
    #pragma unroll
    for (int k = 0; k < 4; k++)
        if (e + k < E && (unsigned)d[k] < (unsigned)N) atomicAdd(&g_deg[d[k]], 1);
}

__global__ void k_scan1(int N) {
    __shared__ int sm[1024];
    int idx = blockIdx.x * 1024 + threadIdx.x;
    int v = (idx < N) ? g_deg[idx] : 0;
    sm[threadIdx.x] = v;
    __syncthreads();
    #pragma unroll
    for (int off = 1; off < 1024; off <<= 1) {
        int t = (threadIdx.x >= off) ? sm[threadIdx.x - off] : 0;
        __syncthreads();
        sm[threadIdx.x] += t;
        __syncthreads();
    }
    if (idx < N) g_rowptr[idx] = sm[threadIdx.x] - v;  // exclusive
    if (threadIdx.x == 1023) g_blksum[blockIdx.x] = sm[1023];
}

// scan3 with inline block-sum prefix: each block reduces blksum[0..b-1] itself (<=98 values)
__global__ void k_scan3(int N, int total) {
    __shared__ int ws[4];
    __shared__ int sh_prefix;
    int b = blockIdx.x;
    int t = threadIdx.x;
    if (t < 128) {
        int lane = t & 31, w = t >> 5;
        int v = (t < b) ? g_blksum[t] : 0;   // b <= 97 < 128
        #pragma unroll
        for (int o = 16; o; o >>= 1) v += __shfl_xor_sync(0xffffffffu, v, o);
        if (lane == 0) ws[w] = v;
    }
    __syncthreads();
    if (t == 0) sh_prefix = ws[0] + ws[1] + ws[2] + ws[3];
    __syncthreads();
    int idx = b * 1024 + t;
    if (idx > N) return;
    if (idx == N) { g_rowptr[N] = total; return; }
    int v = g_rowptr[idx] + sh_prefix;
    g_rowptr[idx] = v;
    g_cursor[idx] = v;
}

__global__ void k_fill(const void* __restrict__ ei, int E, int N) {
    int i = blockIdx.x * blockDim.x + threadIdx.x;
    int E4 = (E + 3) >> 2;
    if (i < E4) {
        int e = i * 4;
        int s[4], d[4];
        if (g_is64) {
            const long long* ps = (const long long*)ei;
            const long long* pd = ps + E;
            longlong4 vs = *(const longlong4*)&ps[e];
            longlong4 vd = *(const longlong4*)&pd[e];
            s[0] = (int)vs.x; s[1] = (int)vs.y; s[2] = (int)vs.z; s[3] = (int)vs.w;
            d[0] = (int)vd.x; d[1] = (int)vd.y; d[2] = (int)vd.z; d[3] = (int)vd.w;
        } else {
            const int* ps = (const int*)ei;
            const int* pd = ps + E;
            int4 vs = *(const int4*)&ps[e];
            int4 vd = *(const int4*)&pd[e];
            s[0] = vs.x; s[1] = vs.y; s[2] = vs.z; s[3] = vs.w;
            d[0] = vd.x; d[1] = vd.y; d[2] = vd.z; d[3] = vd.w;
        }
        #pragma unroll
        for (int k = 0; k < 4; k++) {
            if (e + k >= E) break;
            if ((unsigned)d[k] >= (unsigned)N || (unsigned)s[k] >= (unsigned)N) continue;
            int pos = atomicAdd(&g_cursor[d[k]], 1);
            g_csr[pos] = s[k];
        }
    } else {
        int node = i - E4;
        if (node < N) {
            int pos = atomicAdd(&g_cursor[node], 1);
            g_csr[pos] = node;
        }
    }
}

// ---------------- GEMM1: h1 = x @ W1 [128x64] -> fp16 table, fused alpha epilogue ----------------
// 4x4 register block; accumulators as f32x2 pairs, fma.rn.f32x2 mainloop (8 FFMA2/k vs 16 FFMA).
__global__ void __launch_bounds__(256) k_gemm1(const float* __restrict__ x,
                                               const float* __restrict__ W1,
                                               const float* __restrict__ as,
                                               const float* __restrict__ ad, int N) {
    __shared__ float xs[128 * 68];   // 34.8 KB, transposed x tile
    int t = threadIdx.x;
    int tx = t & 15;                 // cols tx*4 .. tx*4+3
    int ty = t >> 4;                 // rows ty*4 .. ty*4+3
    int head = tx >> 3;
    int base = blockIdx.x * 64;

    float4 as4 = ((const float4*)as)[tx];
    float4 ad4 = ((const float4*)ad)[tx];

    for (int i = t; i < 64 * 128; i += 256) {
        int row = i >> 7, k = i & 127;
        int r = base + row;
        xs[k * 68 + row] = (r < N) ? x[r * 128 + k] : 0.f;
    }
    __syncthreads();

    unsigned long long acc2[4][2] = {};   // [row][colpair]: (c0,c1),(c2,c3)
    #pragma unroll 4
    for (int k = 0; k < 128; k++) {
        float4 w = __ldg((const float4*)&W1[k * 64 + tx * 4]);
        float4 xv = *(const float4*)&xs[k * 68 + ty * 4];
        unsigned long long w01 = pk2(w.x, w.y), w23 = pk2(w.z, w.w);
        unsigned long long x0 = dup2(xv.x), x1 = dup2(xv.y), x2 = dup2(xv.z), x3 = dup2(xv.w);
        fma2(acc2[0][0], x0, w01); fma2(acc2[0][1], x0, w23);
        fma2(acc2[1][0], x1, w01); fma2(acc2[1][1], x1, w23);
        fma2(acc2[2][0], x2, w01); fma2(acc2[2][1], x2, w23);
        fma2(acc2[3][0], x3, w01); fma2(acc2[3][1], x3, w23);
    }

    #pragma unroll
    for (int r = 0; r < 4; r++) {
        int row = base + ty * 4 + r;
        float2 h01 = unpk2(acc2[r][0]);
        float2 h23 = unpk2(acc2[r][1]);
        if (row < N) {
            uint2 pk;
            pk.x = h2_to_u(__floats2half2_rn(h01.x, h01.y));
            pk.y = h2_to_u(__floats2half2_rn(h23.x, h23.y));
            *(uint2*)&g_h1h[row * 64 + tx * 4] = pk;
        }
        float p = h01.x * as4.x + h01.y * as4.y + h23.x * as4.z + h23.y * as4.w;
        float q = h01.x * ad4.x + h01.y * ad4.y + h23.x * ad4.z + h23.y * ad4.w;
        #pragma unroll
        for (int o = 1; o <= 4; o <<= 1) {
            p += __shfl_xor_sync(0xffffffffu, p, o);
            q += __shfl_xor_sync(0xffffffffu, q, o);
        }
        if ((tx & 7) == 0 && row < N) {
            g_as1[row * 2 + head] = p;
            g_ad1[row * 2 + head] = q;
        }
    }
}

// ---------------- Layer1 aggregation: warp-cooperative two-phase ----------------
__global__ void k_agg1(const float* __restrict__ b1, int N) {
    int node = blockIdx.x * 8 + (threadIdx.x >> 5);
    if (node >= N) return;
    int lane = threadIdx.x & 31;
    int hsel = lane >> 4;
    int start = g_rowptr[node], end = g_rowptr[node + 1];
    float2 adp = *(const float2*)&g_ad1[node * 2];
    float2 acc = make_float2(0.f, 0.f);
    float s0 = 0.f, s1 = 0.f;
    for (int b = start; b < end; b += 32) {
        int i = b + lane;
        int src_l = 0; float ex0_l = 0.f, ex1_l = 0.f;
        if (i < end) {
            src_l = g_csr[i];
            float2 a = *(const float2*)&g_as1[src_l * 2];
            ex0_l = __expf(lrelu(a.x + adp.x));
            ex1_l = __expf(lrelu(a.y + adp.y));
        }
        s0 += ex0_l; s1 += ex1_l;
        int cnt = min(32, end - b);
        #pragma unroll 4
        for (int j = 0; j < cnt; j++) {
            int src  = __shfl_sync(0xffffffffu, src_l, j);
            float e0 = __shfl_sync(0xffffffffu, ex0_l, j);
            float e1 = __shfl_sync(0xffffffffu, ex1_l, j);
            float exh = hsel ? e1 : e0;
            float2 v = __half22float2(*(const __half2*)&g_h1h[src * 64 + lane * 2]);
            acc.x += exh * v.x; acc.y += exh * v.y;
        }
    }
    s0 = wsum(s0); s1 = wsum(s1);
    float inv = 1.f / (hsel ? s1 : s0);
    float2 bb = ((const float2*)b1)[lane];
    float2 o = make_float2(fmaxf(acc.x * inv + bb.x, 0.f), fmaxf(acc.y * inv + bb.y, 0.f));
    *(float2*)&g_h1p[node * 64 + lane * 2] = o;
}

// ---------------- GEMM2: h2 = h1p @ W2 [64x128] -> fp16 table, fused alpha2 ----------------
// 4x8 register block; f32x2 accumulators (16 FFMA2/k vs 32 FFMA).
__global__ void __launch_bounds__(256) k_gemm2(const float* __restrict__ W2,
                                               const float* __restrict__ as,
                                               const float* __restrict__ ad, int N) {
    __shared__ float xs[64 * 68];    // 17.4 KB
    int t = threadIdx.x;
    int tx = t & 15;                 // cols tx*8 .. tx*8+7
    int ty = t >> 4;                 // rows ty*4 .. ty*4+3
    int base = blockIdx.x * 64;

    float4 asA = ((const float4*)as)[tx * 2], asB = ((const float4*)as)[tx * 2 + 1];
    float4 adA = ((const float4*)ad)[tx * 2], adB = ((const float4*)ad)[tx * 2 + 1];

    for (int i = t; i < 64 * 64; i += 256) {
        int row = i >> 6, k = i & 63;
        int r = base + row;
        xs[k * 68 + row] = (r < N) ? g_h1p[r * 64 + k] : 0.f;
    }
    __syncthreads();

    unsigned long long acc2[4][4] = {};   // [row][colpair]: 8 cols as 4 pairs
    #pragma unroll 4
    for (int k = 0; k < 64; k++) {
        float4 wa = __ldg((const float4*)&W2[k * 128 + tx * 8]);
        float4 wb = __ldg((const float4*)&W2[k * 128 + tx * 8 + 4]);
        float4 xv = *(const float4*)&xs[k * 68 + ty * 4];
        unsigned long long wp[4] = { pk2(wa.x, wa.y), pk2(wa.z, wa.w),
                                     pk2(wb.x, wb.y), pk2(wb.z, wb.w) };
        unsigned long long xd[4] = { dup2(xv.x), dup2(xv.y), dup2(xv.z), dup2(xv.w) };
        #pragma unroll
        for (int r = 0; r < 4; r++) {
            fma2(acc2[r][0], xd[r], wp[0]);
            fma2(acc2[r][1], xd[r], wp[1]);
            fma2(acc2[r][2], xd[r], wp[2]);
            fma2(acc2[r][3], xd[r], wp[3]);
        }
    }

    #pragma unroll
    for (int r = 0; r < 4; r++) {
        int row = base + ty * 4 + r;
        float2 h0 = unpk2(acc2[r][0]), h1 = unpk2(acc2[r][1]);
        float2 h2 = unpk2(acc2[r][2]), h3 = unpk2(acc2[r][3]);
        if (row < N) {
            uint4 pk;
            pk.x = h2_to_u(__floats2half2_rn(h0.x, h0.y));
            pk.y = h2_to_u(__floats2half2_rn(h1.x, h1.y));
            pk.z = h2_to_u(__floats2half2_rn(h2.x, h2.y));
            pk.w = h2_to_u(__floats2half2_rn(h3.x, h3.y));
            *(uint4*)&g_h2h[row * 128 + tx * 8] = pk;
        }
        float p = h0.x * asA.x + h0.y * asA.y + h1.x * asA.z + h1.y * asA.w
                + h2.x * asB.x + h2.y * asB.y + h3.x * asB.z + h3.y * asB.w;
        float q = h0.x * adA.x + h0.y * adA.y + h1.x * adA.z + h1.y * adA.w
                + h2.x * adB.x + h2.y * adB.y + h3.x * adB.z + h3.y * adB.w;
        #pragma unroll
        for (int o = 1; o <= 8; o <<= 1) {
            p += __shfl_xor_sync(0xffffffffu, p, o);
            q += __shfl_xor_sync(0xffffffffu, q, o);
        }
        if (tx == 0 && row < N) { g_as2[row] = p; g_ad2[row] = q; }
    }
}

// ---------------- Layer2 aggregation: warp-cooperative two-phase, fp16 gather ----------------
__global__ void k_agg2(const float* __restrict__ b2, int N, float* __restrict__ out) {
    int node = blockIdx.x * 8 + (threadIdx.x >> 5);
    if (node >= N) return;
    int lane = threadIdx.x & 31;
    int start = g_rowptr[node], end = g_rowptr[node + 1];
    float ad = g_ad2[node];
    float4 acc = make_float4(0.f, 0.f, 0.f, 0.f);
    float spart = 0.f;
    for (int b = start; b < end; b += 32) {
        int i = b + lane;
        int src_l = 0; float ex_l = 0.f;
        if (i < end) {
            src_l = g_csr[i];
            ex_l = __expf(lrelu(g_as2[src_l] + ad));
        }
        spart += ex_l;
        int cnt = min(32, end - b);
        #pragma unroll 4
        for (int j = 0; j < cnt; j++) {
            int src  = __shfl_sync(0xffffffffu, src_l, j);
            float ex = __shfl_sync(0xffffffffu, ex_l, j);
            uint2 pk = *(const uint2*)&g_h2h[src * 128 + lane * 4];
            float2 v0 = __half22float2(u_to_h2(pk.x));
            float2 v1 = __half22float2(u_to_h2(pk.y));
            acc.x += ex * v0.x; acc.y += ex * v0.y;
            acc.z += ex * v1.x; acc.w += ex * v1.y;
        }
    }
    float inv = 1.f / wsum(spart);
    float4 bb = ((const float4*)b2)[lane];
    float4 o;
    o.x = acc.x * inv + bb.x;
    o.y = acc.y * inv + bb.y;
    o.z = acc.z * inv + bb.z;
    o.w = acc.w * inv + bb.w;
    ((float4*)out)[node * 32 + lane] = o;
}

// ---------------- launch: fork CSR build onto a side stream, overlap with GEMM1 ----------------
extern "C" void kernel_launch(void* const* d_in, const int* in_sizes, int n_in,
                              void* d_out, int out_size) {
    const float* x   = (const float*)d_in[0];
    const void*  ei  = d_in[1];
    const float* W1  = (const float*)d_in[2];
    const float* as1 = (const float*)d_in[3];
    const float* ad1 = (const float*)d_in[4];
    const float* b1  = (const float*)d_in[5];
    const float* W2  = (const float*)d_in[6];
    const float* as2 = (const float*)d_in[7];
    const float* ad2 = (const float*)d_in[8];
    const float* b2  = (const float*)d_in[9];
    float* out = (float*)d_out;

    int N = in_sizes[0] / 128;
    int E = in_sizes[1] / 2;

    static cudaStream_t s2 = nullptr;
    static cudaEvent_t evFork = nullptr, evJoin = nullptr;
    if (!s2) {
        cudaStreamCreateWithFlags(&s2, cudaStreamNonBlocking);
        cudaEventCreateWithFlags(&evFork, cudaEventDisableTiming);
        cudaEventCreateWithFlags(&evJoin, cudaEventDisableTiming);
    }

    // fork: CSR build on s2
    cudaEventRecord(evFork, 0);
    cudaStreamWaitEvent(s2, evFork, 0);
    k_init_deg<<<(N + 255) / 256, 256, 0, s2>>>(ei, N);
    k_count<<<(E / 4 + 255) / 256, 256, 0, s2>>>(ei, E, N);
    int nb = (N + 1023) / 1024;
    k_scan1<<<nb, 1024, 0, s2>>>(N);
    k_scan3<<<nb, 1024, 0, s2>>>(N, E + N);
    {
        int E4 = (E + 3) / 4;
        k_fill<<<(E4 + N + 255) / 256, 256, 0, s2>>>(ei, E, N);
    }
    cudaEventRecord(evJoin, s2);

    // concurrent: GEMM1 on the main (capture) stream
    int ng = (N + 63) / 64;
    k_gemm1<<<ng, 256>>>(x, W1, as1, ad1, N);

    // join, then the dependent tail
    cudaStreamWaitEvent(0, evJoin, 0);
    k_agg1<<<(N + 7) / 8, 256>>>(b1, N);
    k_gemm2<<<ng, 256>>>(W2, as2, ad2, N);
    k_agg2<<<(N + 7) / 8, 256>>>(b2, N, out);
}